// round 13
// baseline (speedup 1.0000x reference)
#include <cuda_runtime.h>
#include <cuda_bf16.h>
#include <math.h>
#include <stdint.h>
#include <stddef.h>

// Problem dims (fixed by the dataset)
#define BD   2560
#define SW   50
#define EW   200
#define HH   128
#define BB   64
#define DD   40
#define GC   256
#define CC   128

typedef unsigned long long ull;

// ---------------- packed fp32x2 helpers ----------------
__device__ __forceinline__ ull ffma2(ull a, ull b, ull c) {
    ull d;
    asm("fma.rn.f32x2 %0, %1, %2, %3;" : "=l"(d) : "l"(a), "l"(b), "l"(c));
    return d;
}
__device__ __forceinline__ ull pack2(float x, float y) {
    ull d;
    asm("mov.b64 %0, {%1, %2};" : "=l"(d) : "r"(__float_as_uint(x)), "r"(__float_as_uint(y)));
    return d;
}
__device__ __forceinline__ float2 unpack2(ull v) {
    unsigned lo, hi;
    asm("mov.b64 {%0, %1}, %2;" : "=r"(lo), "=r"(hi) : "l"(v));
    float2 r; r.x = __uint_as_float(lo); r.y = __uint_as_float(hi);
    return r;
}

// ---------------- mma.sync bf16 (legacy HMMA, sm_80+ PTX -> valid on sm_103) -----
__device__ __forceinline__ void mma16816(float* c, const uint32_t* a, const uint32_t* b) {
    asm volatile(
        "mma.sync.aligned.m16n8k16.row.col.f32.bf16.bf16.f32 "
        "{%0,%1,%2,%3}, {%4,%5,%6,%7}, {%8,%9}, {%0,%1,%2,%3};"
        : "+f"(c[0]), "+f"(c[1]), "+f"(c[2]), "+f"(c[3])
        : "r"(a[0]), "r"(a[1]), "r"(a[2]), "r"(a[3]), "r"(b[0]), "r"(b[1]));
}

// ---------------- scratch (device globals) ----------------
__device__ float g_XWg_f[(size_t)BD*SW*GC];
__device__ float g_XWc_f[(size_t)BD*SW*CC];
__device__ float g_XWg_b[(size_t)BD*SW*GC];
__device__ float g_XWc_b[(size_t)BD*SW*CC];
__device__ float g_low  [(size_t)BD*SW*GC];
__device__ float g_proj [(size_t)BD*SW*CC];
__device__ float g_sent[BD*GC];
__device__ float g_sXWg_f[BB*DD*GC];
__device__ float g_sXWc_f[BB*DD*CC];
__device__ float g_sXWg_b[BB*DD*GC];
__device__ float g_sXWc_b[BB*DD*CC];
__device__ float g_high[BB*DD*GC];
__device__ float g_docvec[BB*GC];

// ============ tensor-core GEMM (split-bf16, mma.sync): C = A @ W + bias =========
// Block computes C[m0:m0+128, n0:n0+128]. fp32 = bf16hi + bf16lo; three products
// AhiBhi + AloBhi + AhiBlo accumulated in f32. 8 warps x (32x64) subtiles.
#define KCH 32
#define AST 40   // padded tile stride in bf16 elems (conflict-free fragment loads)

__global__ void __launch_bounds__(256, 2)
hgemm_bias(const float* __restrict__ A, const float* __restrict__ W,
           const float* __restrict__ bias, float* __restrict__ C,
           int srcK, int Nout, int act)
{
    __shared__ __align__(16) __nv_bfloat16 sAhi[128 * AST];
    __shared__ __align__(16) __nv_bfloat16 sAlo[128 * AST];
    __shared__ __align__(16) __nv_bfloat16 sBhi[128 * AST];
    __shared__ __align__(16) __nv_bfloat16 sBlo[128 * AST];

    const int tid = threadIdx.x;
    const int wid = tid >> 5, lane = tid & 31;
    const int wr = wid & 3, wc = wid >> 2;       // warp row/col block
    const int gid = lane >> 2, tig = lane & 3;
    const int m0 = blockIdx.x * 128;
    const int n0 = blockIdx.y * 128;

    float acc[2][8][4];
#pragma unroll
    for (int mt = 0; mt < 2; mt++)
#pragma unroll
        for (int nt = 0; nt < 8; nt++)
#pragma unroll
            for (int i = 0; i < 4; i++) acc[mt][nt][i] = 0.f;

    const int nch = (srcK + KCH - 1) / KCH;
    for (int ch = 0; ch < nch; ch++) {
        const int kb = ch * KCH;
        __syncthreads();
        // fill A tile [128 rows x 32 k] hi/lo (coalesced row reads)
        for (int idx = tid; idx < 128 * KCH; idx += 256) {
            int r = idx >> 5, k = idx & 31;
            float x = (kb + k < srcK) ? A[(size_t)(m0 + r) * srcK + kb + k] : 0.f;
            __nv_bfloat16 h = __float2bfloat16(x);
            sAhi[r * AST + k] = h;
            sAlo[r * AST + k] = __float2bfloat16(x - __bfloat162float(h));
        }
        // fill B tile = W^T [128 n x 32 k] hi/lo (coalesced n reads)
        for (int idx = tid; idx < 128 * KCH; idx += 256) {
            int k = idx >> 7, n = idx & 127;
            float x = (kb + k < srcK) ? W[(size_t)(kb + k) * Nout + n0 + n] : 0.f;
            __nv_bfloat16 h = __float2bfloat16(x);
            sBhi[n * AST + k] = h;
            sBlo[n * AST + k] = __float2bfloat16(x - __bfloat162float(h));
        }
        __syncthreads();

#pragma unroll
        for (int ks = 0; ks < 2; ks++) {
            const int kk = ks * 16 + tig * 2;
            uint32_t ah[2][4], al[2][4];
#pragma unroll
            for (int mt = 0; mt < 2; mt++) {
                int r = wr * 32 + mt * 16 + gid;
                ah[mt][0] = *(const uint32_t*)&sAhi[r * AST + kk];
                ah[mt][1] = *(const uint32_t*)&sAhi[(r + 8) * AST + kk];
                ah[mt][2] = *(const uint32_t*)&sAhi[r * AST + kk + 8];
                ah[mt][3] = *(const uint32_t*)&sAhi[(r + 8) * AST + kk + 8];
                al[mt][0] = *(const uint32_t*)&sAlo[r * AST + kk];
                al[mt][1] = *(const uint32_t*)&sAlo[(r + 8) * AST + kk];
                al[mt][2] = *(const uint32_t*)&sAlo[r * AST + kk + 8];
                al[mt][3] = *(const uint32_t*)&sAlo[(r + 8) * AST + kk + 8];
            }
#pragma unroll
            for (int nt = 0; nt < 8; nt++) {
                int n = wc * 64 + nt * 8 + gid;
                uint32_t bh[2], bl[2];
                bh[0] = *(const uint32_t*)&sBhi[n * AST + kk];
                bh[1] = *(const uint32_t*)&sBhi[n * AST + kk + 8];
                bl[0] = *(const uint32_t*)&sBlo[n * AST + kk];
                bl[1] = *(const uint32_t*)&sBlo[n * AST + kk + 8];
#pragma unroll
                for (int mt = 0; mt < 2; mt++) {
                    mma16816(acc[mt][nt], ah[mt], bh);
                    mma16816(acc[mt][nt], al[mt], bh);
                    mma16816(acc[mt][nt], ah[mt], bl);
                }
            }
        }
    }

    // epilogue: bias + optional tanh, direct f32 stores
#pragma unroll
    for (int mt = 0; mt < 2; mt++) {
        int r = m0 + wr * 32 + mt * 16 + gid;
#pragma unroll
        for (int nt = 0; nt < 8; nt++) {
            int col = n0 + wc * 64 + nt * 8 + tig * 2;
            float b0 = bias[col], b1 = bias[col + 1];
            float2 v0, v1;
            v0.x = acc[mt][nt][0] + b0; v0.y = acc[mt][nt][1] + b1;
            v1.x = acc[mt][nt][2] + b0; v1.y = acc[mt][nt][3] + b1;
            if (act) {
                v0.x = tanhf(v0.x); v0.y = tanhf(v0.y);
                v1.x = tanhf(v1.x); v1.y = tanhf(v1.y);
            }
            *(float2*)(C + (size_t)r * Nout + col) = v0;
            *(float2*)(C + (size_t)(r + 8) * Nout + col) = v1;
        }
    }
}

// ---------------- WORD-LEVEL BiGRU: 512 threads, resident weights ----------------
#define WSPB 20
__global__ void __launch_bounds__(512, 1)
gru_word_kernel(
    const float* __restrict__ XWg0, const float* __restrict__ XWg1,
    const float* __restrict__ XWc0, const float* __restrict__ XWc1,
    const float* __restrict__ Wgh0, const float* __restrict__ Wgh1,
    const float* __restrict__ Wch0, const float* __restrict__ Wch1,
    const int*   __restrict__ lens,
    float* __restrict__ outp, int T)
{
    const int dir = blockIdx.y;
    const float* XWg = dir ? XWg1 : XWg0;
    const float* XWc = dir ? XWc1 : XWc0;
    const float* Wgh = dir ? Wgh1 : Wgh0;
    const float* Wch = dir ? Wch1 : Wch0;
    const int col_off = dir * CC;

    extern __shared__ float smemf[];
    float* swg = smemf;
    float* swc = swg + HH * GC;
    float* sh  = swc + HH * CC;
    float* srh = sh  + WSPB * HH;
    float* sz  = srh + WSPB * HH;
    int*   slen = (int*)(sz + WSPB * HH);

    const int tid = threadIdx.x;
    const int nb  = blockIdx.x * WSPB;
    if (tid < WSPB) slen[tid] = lens[nb + tid];

    {
        const float4* src = (const float4*)Wgh;
        float4* dst = (float4*)swg;
        for (int i = tid; i < HH * GC / 4; i += 512) dst[i] = src[i];
        src = (const float4*)Wch;
        dst = (float4*)swc;
        for (int i = tid; i < HH * CC / 4; i += 512) dst[i] = src[i];
    }
    for (int i = tid; i < WSPB * HH; i += 512) sh[i] = 0.f;
    __syncthreads();

    const int ct = tid & 63;
    const int rt = tid >> 6;
    const int j0 = ct * 4;
    const int j2 = ct * 2;
    const int srn = (rt < 4) ? 3 : 2;
    const int s0  = (rt < 4) ? rt * 3 : 12 + (rt - 4) * 2;

    for (int t = 0; t < T; t++) {
        int   te_s[3]; bool val_s[3];
        float4 xg[3]; float2 xc[3];
#pragma unroll
        for (int s = 0; s < 3; s++) {
            if (s < srn) {
                int sl = s0 + s;
                int L  = slen[sl];
                bool valid = (t < L);
                int te = dir ? (valid ? (L - 1 - t) : t) : t;
                te_s[s] = te; val_s[s] = valid;
                int n = nb + sl;
                xg[s] = *(const float4*)(XWg + ((size_t)n * T + te) * GC + j0);
                xc[s] = *(const float2*)(XWc + ((size_t)n * T + te) * CC + j2);
            }
        }

        ull a0[3], a1[3];
#pragma unroll
        for (int s = 0; s < 3; s++) { a0[s] = 0ull; a1[s] = 0ull; }

#pragma unroll 4
        for (int kc = 0; kc < HH; kc += 4) {
            ulonglong2 w0 = *(const ulonglong2*)(swg + (size_t)(kc + 0) * GC + j0);
            ulonglong2 w1 = *(const ulonglong2*)(swg + (size_t)(kc + 1) * GC + j0);
            ulonglong2 w2 = *(const ulonglong2*)(swg + (size_t)(kc + 2) * GC + j0);
            ulonglong2 w3 = *(const ulonglong2*)(swg + (size_t)(kc + 3) * GC + j0);
#pragma unroll
            for (int s = 0; s < 3; s++) {
                if (s < srn) {
                    float4 hv = *(const float4*)(sh + (s0 + s) * HH + kc);
                    ull ap;
                    ap = pack2(hv.x, hv.x);
                    a0[s] = ffma2(ap, w0.x, a0[s]); a1[s] = ffma2(ap, w0.y, a1[s]);
                    ap = pack2(hv.y, hv.y);
                    a0[s] = ffma2(ap, w1.x, a0[s]); a1[s] = ffma2(ap, w1.y, a1[s]);
                    ap = pack2(hv.z, hv.z);
                    a0[s] = ffma2(ap, w2.x, a0[s]); a1[s] = ffma2(ap, w2.y, a1[s]);
                    ap = pack2(hv.w, hv.w);
                    a0[s] = ffma2(ap, w3.x, a0[s]); a1[s] = ffma2(ap, w3.y, a1[s]);
                }
            }
        }

#pragma unroll
        for (int s = 0; s < 3; s++) {
            if (s < srn) {
                int sl = s0 + s;
                float2 g01 = unpack2(a0[s]);
                float2 g23 = unpack2(a1[s]);
                float v0 = 1.f / (1.f + expf(-(g01.x + xg[s].x)));
                float v1 = 1.f / (1.f + expf(-(g01.y + xg[s].y)));
                float v2 = 1.f / (1.f + expf(-(g23.x + xg[s].z)));
                float v3 = 1.f / (1.f + expf(-(g23.y + xg[s].w)));
                if (ct < 32) {
                    float4 hv = *(const float4*)(sh + sl * HH + j0);
                    float4 o; o.x = v0 * hv.x; o.y = v1 * hv.y; o.z = v2 * hv.z; o.w = v3 * hv.w;
                    *(float4*)(srh + sl * HH + j0) = o;
                } else {
                    float4 o; o.x = v0; o.y = v1; o.z = v2; o.w = v3;
                    *(float4*)(sz + sl * HH + (j0 - 128)) = o;
                }
            }
        }
        __syncthreads();

        ull c2[3];
#pragma unroll
        for (int s = 0; s < 3; s++) c2[s] = 0ull;

#pragma unroll 4
        for (int kc = 0; kc < HH; kc += 4) {
            ull w0 = *(const ull*)(swc + (size_t)(kc + 0) * CC + j2);
            ull w1 = *(const ull*)(swc + (size_t)(kc + 1) * CC + j2);
            ull w2 = *(const ull*)(swc + (size_t)(kc + 2) * CC + j2);
            ull w3 = *(const ull*)(swc + (size_t)(kc + 3) * CC + j2);
#pragma unroll
            for (int s = 0; s < 3; s++) {
                if (s < srn) {
                    float4 rv = *(const float4*)(srh + (s0 + s) * HH + kc);
                    c2[s] = ffma2(pack2(rv.x, rv.x), w0, c2[s]);
                    c2[s] = ffma2(pack2(rv.y, rv.y), w1, c2[s]);
                    c2[s] = ffma2(pack2(rv.z, rv.z), w2, c2[s]);
                    c2[s] = ffma2(pack2(rv.w, rv.w), w3, c2[s]);
                }
            }
        }

#pragma unroll
        for (int s = 0; s < 3; s++) {
            if (s < srn) {
                int sl = s0 + s;
                int n  = nb + sl;
                bool valid = val_s[s];
                int te = te_s[s];
                float2 cc = unpack2(c2[s]);
                float c0 = tanhf(cc.x + xc[s].x);
                float c1 = tanhf(cc.y + xc[s].y);
                float2 zv = *(const float2*)(sz + sl * HH + j2);
                float2 hv = *(const float2*)(sh + sl * HH + j2);
                float hn0 = zv.x * hv.x + (1.f - zv.x) * c0;
                float hn1 = zv.y * hv.y + (1.f - zv.y) * c1;
                float2 hw; hw.x = valid ? hn0 : hv.x; hw.y = valid ? hn1 : hv.y;
                *(float2*)(sh + sl * HH + j2) = hw;
                float2 ov; ov.x = valid ? hn0 : 0.f; ov.y = valid ? hn1 : 0.f;
                *(float2*)(outp + ((size_t)n * T + te) * GC + col_off + j2) = ov;
            }
        }
        __syncthreads();
    }
}

// ---------------- sentence-level BiGRU: 256 threads, resident weights ------------
template<int SPB>
__global__ void __launch_bounds__(256, 1)
gru_resident_kernel(
    const float* __restrict__ XWg0, const float* __restrict__ XWg1,
    const float* __restrict__ XWc0, const float* __restrict__ XWc1,
    const float* __restrict__ Wgh0, const float* __restrict__ Wgh1,
    const float* __restrict__ Wch0, const float* __restrict__ Wch1,
    const int*   __restrict__ lens,
    float* __restrict__ outp, int T)
{
    constexpr int SR = SPB / 4;
    const int dir = blockIdx.y;
    const float* XWg = dir ? XWg1 : XWg0;
    const float* XWc = dir ? XWc1 : XWc0;
    const float* Wgh = dir ? Wgh1 : Wgh0;
    const float* Wch = dir ? Wch1 : Wch0;
    const int col_off = dir * CC;

    extern __shared__ float smemf[];
    float* swg = smemf;
    float* swc = swg + HH * GC;
    float* sh  = swc + HH * CC;
    float* srh = sh  + SPB * HH;
    float* sz  = srh + SPB * HH;
    int*   slen = (int*)(sz + SPB * HH);

    const int tid = threadIdx.x;
    const int nb  = blockIdx.x * SPB;
    if (tid < SPB) slen[tid] = lens[nb + tid];

    {
        const float4* src = (const float4*)Wgh;
        float4* dst = (float4*)swg;
        for (int i = tid; i < HH * GC / 4; i += 256) dst[i] = src[i];
        src = (const float4*)Wch;
        dst = (float4*)swc;
        for (int i = tid; i < HH * CC / 4; i += 256) dst[i] = src[i];
    }
    for (int i = tid; i < SPB * HH; i += 256) sh[i] = 0.f;
    __syncthreads();

    const int ct = tid & 63, rt = tid >> 6;
    const int j0 = ct * 4;
    const int j2 = ct * 2;
    const int s0 = rt * SR;

    for (int t = 0; t < T; t++) {
        ull accg[SR][2];
#pragma unroll
        for (int s = 0; s < SR; s++) { accg[s][0] = 0ull; accg[s][1] = 0ull; }

#pragma unroll 4
        for (int kc = 0; kc < HH; kc += 4) {
            ulonglong2 w0 = *(const ulonglong2*)(swg + (size_t)(kc + 0) * GC + j0);
            ulonglong2 w1 = *(const ulonglong2*)(swg + (size_t)(kc + 1) * GC + j0);
            ulonglong2 w2 = *(const ulonglong2*)(swg + (size_t)(kc + 2) * GC + j0);
            ulonglong2 w3 = *(const ulonglong2*)(swg + (size_t)(kc + 3) * GC + j0);
#pragma unroll
            for (int s = 0; s < SR; s++) {
                float4 hv = *(const float4*)(sh + (s0 + s) * HH + kc);
                ull ap;
                ap = pack2(hv.x, hv.x);
                accg[s][0] = ffma2(ap, w0.x, accg[s][0]); accg[s][1] = ffma2(ap, w0.y, accg[s][1]);
                ap = pack2(hv.y, hv.y);
                accg[s][0] = ffma2(ap, w1.x, accg[s][0]); accg[s][1] = ffma2(ap, w1.y, accg[s][1]);
                ap = pack2(hv.z, hv.z);
                accg[s][0] = ffma2(ap, w2.x, accg[s][0]); accg[s][1] = ffma2(ap, w2.y, accg[s][1]);
                ap = pack2(hv.w, hv.w);
                accg[s][0] = ffma2(ap, w3.x, accg[s][0]); accg[s][1] = ffma2(ap, w3.y, accg[s][1]);
            }
        }

#pragma unroll
        for (int s = 0; s < SR; s++) {
            int sl = s0 + s;
            int n  = nb + sl;
            int L  = slen[sl];
            int te = dir ? ((t < L) ? (L - 1 - t) : t) : t;
            float4 xg = *(const float4*)(XWg + ((size_t)n * T + te) * GC + j0);
            float2 g01 = unpack2(accg[s][0]);
            float2 g23 = unpack2(accg[s][1]);
            float v0 = 1.f / (1.f + expf(-(g01.x + xg.x)));
            float v1 = 1.f / (1.f + expf(-(g01.y + xg.y)));
            float v2 = 1.f / (1.f + expf(-(g23.x + xg.z)));
            float v3 = 1.f / (1.f + expf(-(g23.y + xg.w)));
            if (ct < 32) {
                float4 hv = *(const float4*)(sh + sl * HH + j0);
                float4 o; o.x = v0 * hv.x; o.y = v1 * hv.y; o.z = v2 * hv.z; o.w = v3 * hv.w;
                *(float4*)(srh + sl * HH + j0) = o;
            } else {
                float4 o; o.x = v0; o.y = v1; o.z = v2; o.w = v3;
                *(float4*)(sz + sl * HH + (j0 - 128)) = o;
            }
        }
        __syncthreads();

        ull accc[SR];
#pragma unroll
        for (int s = 0; s < SR; s++) accc[s] = 0ull;

#pragma unroll 4
        for (int kc = 0; kc < HH; kc += 4) {
            ull w0 = *(const ull*)(swc + (size_t)(kc + 0) * CC + j2);
            ull w1 = *(const ull*)(swc + (size_t)(kc + 1) * CC + j2);
            ull w2 = *(const ull*)(swc + (size_t)(kc + 2) * CC + j2);
            ull w3 = *(const ull*)(swc + (size_t)(kc + 3) * CC + j2);
#pragma unroll
            for (int s = 0; s < SR; s++) {
                float4 hv = *(const float4*)(srh + (s0 + s) * HH + kc);
                accc[s] = ffma2(pack2(hv.x, hv.x), w0, accc[s]);
                accc[s] = ffma2(pack2(hv.y, hv.y), w1, accc[s]);
                accc[s] = ffma2(pack2(hv.z, hv.z), w2, accc[s]);
                accc[s] = ffma2(pack2(hv.w, hv.w), w3, accc[s]);
            }
        }

#pragma unroll
        for (int s = 0; s < SR; s++) {
            int sl = s0 + s;
            int n  = nb + sl;
            int L  = slen[sl];
            bool valid = (t < L);
            int te = dir ? (valid ? (L - 1 - t) : t) : t;
            float2 xc = *(const float2*)(XWc + ((size_t)n * T + te) * CC + j2);
            float2 cc = unpack2(accc[s]);
            float c0 = tanhf(cc.x + xc.x);
            float c1 = tanhf(cc.y + xc.y);
            float z0 = sz[sl * HH + j2], z1 = sz[sl * HH + j2 + 1];
            float h0 = sh[sl * HH + j2], h1 = sh[sl * HH + j2 + 1];
            float hn0 = z0 * h0 + (1.f - z0) * c0;
            float hn1 = z1 * h1 + (1.f - z1) * c1;
            float2 hw; hw.x = valid ? hn0 : h0; hw.y = valid ? hn1 : h1;
            *(float2*)(sh + sl * HH + j2) = hw;
            float2 ov; ov.x = valid ? hn0 : 0.f; ov.y = valid ? hn1 : 0.f;
            *(float2*)(outp + ((size_t)n * T + te) * GC + col_off + j2) = ov;
        }
        __syncthreads();
    }
}

// ---------------- attention ------------------------------------------------------
__global__ void attention_kernel(const float* __restrict__ proj,
                                 const float* __restrict__ u,
                                 const float* __restrict__ seq,
                                 float* __restrict__ vec,
                                 float* __restrict__ att_out,
                                 int N, int T)
{
    const int n = blockIdx.x;
    const int tid = threadIdx.x;
    const int warp = tid >> 5, lane = tid & 31;
    __shared__ float su[128];
    __shared__ float sc[64];
    __shared__ float red[2];
    if (tid < 128) su[tid] = u[tid];
    __syncthreads();

    for (int t = warp; t < T; t += 8) {
        const float* pr = proj + ((size_t)n * T + t) * 128;
        float p = 0.f;
#pragma unroll
        for (int i = 0; i < 4; i++) p += pr[lane + i * 32] * su[lane + i * 32];
#pragma unroll
        for (int o = 16; o > 0; o >>= 1) p += __shfl_xor_sync(0xffffffffu, p, o);
        if (lane == 0) sc[t] = p;
    }
    __syncthreads();
    if (tid == 0) {
        float m = sc[0];
        for (int t = 1; t < T; t++) m = fmaxf(m, sc[t]);
        float s = 0.f;
        for (int t = 0; t < T; t++) s += expf(sc[t] - m);
        red[0] = m; red[1] = s;
    }
    __syncthreads();
    if (tid < T) {
        float a = expf(sc[tid] - red[0]) / red[1];
        att_out[(size_t)n * T + tid] = a;
        sc[tid] = a;
    }
    __syncthreads();
    {
        int c = tid;
        float a = 0.f;
        for (int t = 0; t < T; t++) a += sc[t] * seq[((size_t)n * T + t) * 256 + c];
        vec[(size_t)n * 256 + c] = a;
    }
}

// ---------------- final ----------------------------------------------------------
__global__ void final_kernel(const float* __restrict__ docvec, const float* __restrict__ wp,
                             const float* __restrict__ bp, const int* __restrict__ y,
                             const float* __restrict__ wa_l, const float* __restrict__ ba_l,
                             const float* __restrict__ wa_h, const float* __restrict__ uw,
                             const float* __restrict__ us, float* __restrict__ out)
{
    __shared__ float slog[640];
    __shared__ float red[256];
    __shared__ float lossb[64];
    __shared__ int corr[64];
    const int tid = threadIdx.x;

    for (int idx = tid; idx < 640; idx += 256) {
        int b = idx / 10, c = idx % 10;
        float a = bp[c];
        for (int k = 0; k < 256; k++) a += docvec[b * 256 + k] * wp[k * 10 + c];
        slog[idx] = a;
    }
    __syncthreads();
    if (tid < 64) {
        int b = tid;
        float m = slog[b * 10]; int am = 0;
        for (int c = 1; c < 10; c++) { float v = slog[b * 10 + c]; if (v > m) { m = v; am = c; } }
        float s = 0.f;
        for (int c = 0; c < 10; c++) s += expf(slog[b * 10 + c] - m);
        float lse = m + logf(s);
        int yb = y[b];
        lossb[b] = lse - slog[b * 10 + yb];
        corr[b]  = (am == yb) ? 1 : 0;
        out[1 + b] = (float)am;
    }
    float r = 0.f;
    for (int i = tid; i < 256 * 128; i += 256) {
        float v = wa_l[i]; r += v * v;
        float w = wa_h[i]; r += 2.f * w * w;
    }
    for (int i = tid; i < 128; i += 256) {
        float v = ba_l[i]; r += v * v;
        float a = uw[i];   r += a * a;
        float b2 = us[i];  r += b2 * b2;
    }
    red[tid] = r;
    __syncthreads();
    for (int o = 128; o > 0; o >>= 1) { if (tid < o) red[tid] += red[tid + o]; __syncthreads(); }
    if (tid == 0) {
        float L = 0.f; int C = 0;
        for (int b = 0; b < 64; b++) { L += lossb[b]; C += corr[b]; }
        out[0]  = L / 64.f + 0.01f * red[0];
        out[65] = (float)C / 64.f;
    }
}

// =================================================================================
extern "C" void kernel_launch(void* const* d_in, const int* in_sizes, int n_in,
                              void* d_out, int out_size)
{
    (void)in_sizes; (void)out_size;
    const float* X    = (const float*)d_in[0];
    const int*   y    = (const int*)d_in[1];
    const int*   slen = (const int*)d_in[2];
    const int*   dlen = (const int*)d_in[3];
    const int wo = (n_in >= 30) ? 6 : (n_in - 24);
    const float* Wt[24];
    for (int i = 0; i < 24; i++) Wt[i] = (const float*)d_in[wo + i];
    const float *wgf_l = Wt[0],  *bgf_l = Wt[1],  *wcf_l = Wt[2],  *bcf_l = Wt[3];
    const float *wgb_l = Wt[4],  *bgb_l = Wt[5],  *wcb_l = Wt[6],  *bcb_l = Wt[7];
    const float *wa_l  = Wt[8],  *ba_l  = Wt[9];
    const float *wgf_h = Wt[10], *bgf_h = Wt[11], *wcf_h = Wt[12], *bcf_h = Wt[13];
    const float *wgb_h = Wt[14], *bgb_h = Wt[15], *wcb_h = Wt[16], *bcb_h = Wt[17];
    const float *wa_h  = Wt[18], *ba_h  = Wt[19];
    const float *uw = Wt[20], *us = Wt[21], *wp = Wt[22], *bp = Wt[23];
    float* out = (float*)d_out;

    float *XWg_f, *XWc_f, *XWg_b, *XWc_b, *low, *proj, *sent;
    float *sXWg_f, *sXWc_f, *sXWg_b, *sXWc_b, *high, *docvec;
    cudaGetSymbolAddress((void**)&XWg_f, g_XWg_f);
    cudaGetSymbolAddress((void**)&XWc_f, g_XWc_f);
    cudaGetSymbolAddress((void**)&XWg_b, g_XWg_b);
    cudaGetSymbolAddress((void**)&XWc_b, g_XWc_b);
    cudaGetSymbolAddress((void**)&low,   g_low);
    cudaGetSymbolAddress((void**)&proj,  g_proj);
    cudaGetSymbolAddress((void**)&sent,  g_sent);
    cudaGetSymbolAddress((void**)&sXWg_f, g_sXWg_f);
    cudaGetSymbolAddress((void**)&sXWc_f, g_sXWc_f);
    cudaGetSymbolAddress((void**)&sXWg_b, g_sXWg_b);
    cudaGetSymbolAddress((void**)&sXWc_b, g_sXWc_b);
    cudaGetSymbolAddress((void**)&high,  g_high);
    cudaGetSymbolAddress((void**)&docvec, g_docvec);

    const int smem_w = (HH * GC + HH * CC + 3 * WSPB * HH) * 4 + WSPB * 4;  // 227,408 B
    const int smem_s = (HH * GC + HH * CC + 3 * 4 * HH) * 4 + 4 * 4;
    cudaFuncSetAttribute(gru_word_kernel, cudaFuncAttributeMaxDynamicSharedMemorySize, smem_w);
    cudaFuncSetAttribute(gru_resident_kernel<4>, cudaFuncAttributeMaxDynamicSharedMemorySize, smem_s);

    const int MW = BD * SW / 128;   // 1000 word-level M-tiles
    const int MS = BB * DD / 128;   // 20 sentence-level M-tiles

    // 1) word-level input precompute (tensor cores via mma.sync, split-bf16)
    hgemm_bias<<<dim3(MW, 2), 256>>>(X, wgf_l, bgf_l, XWg_f, EW, GC, 0);
    hgemm_bias<<<dim3(MW, 1), 256>>>(X, wcf_l, bcf_l, XWc_f, EW, CC, 0);
    hgemm_bias<<<dim3(MW, 2), 256>>>(X, wgb_l, bgb_l, XWg_b, EW, GC, 0);
    hgemm_bias<<<dim3(MW, 1), 256>>>(X, wcb_l, bcb_l, XWc_b, EW, CC, 0);

    // 2) word-level BiGRU
    gru_word_kernel<<<dim3(BD / WSPB, 2), 512, smem_w>>>(
        XWg_f, XWg_b, XWc_f, XWc_b,
        wgf_l + (size_t)EW * GC, wgb_l + (size_t)EW * GC,
        wcf_l + (size_t)EW * CC, wcb_l + (size_t)EW * CC,
        slen, low, SW);

    // 3) word attention
    hgemm_bias<<<dim3(MW, 1), 256>>>(low, wa_l, ba_l, proj, GC, CC, 1);
    attention_kernel<<<BD, 256>>>(proj, uw, low, sent, out + 66, BD, SW);

    // 4) sentence-level input precompute
    hgemm_bias<<<dim3(MS, 2), 256>>>(sent, wgf_h, bgf_h, sXWg_f, GC, GC, 0);
    hgemm_bias<<<dim3(MS, 1), 256>>>(sent, wcf_h, bcf_h, sXWc_f, GC, CC, 0);
    hgemm_bias<<<dim3(MS, 2), 256>>>(sent, wgb_h, bgb_h, sXWg_b, GC, GC, 0);
    hgemm_bias<<<dim3(MS, 1), 256>>>(sent, wcb_h, bcb_h, sXWc_b, GC, CC, 0);

    // 5) sentence-level BiGRU
    gru_resident_kernel<4><<<dim3(BB / 4, 2), 256, smem_s>>>(
        sXWg_f, sXWg_b, sXWc_f, sXWc_b,
        wgf_h + (size_t)GC * GC, wgb_h + (size_t)GC * GC,
        wcf_h + (size_t)GC * CC, wcb_h + (size_t)GC * CC,
        dlen, high, DD);

    // 6) sentence attention
    hgemm_bias<<<dim3(MS, 1), 256>>>(high, wa_h, ba_h, proj, GC, CC, 1);
    attention_kernel<<<BB, 256>>>(proj, us, high, docvec, out + 66 + BD * SW, BB, DD);

    // 7) classifier / loss / reg / predict / accuracy
    final_kernel<<<1, 256>>>(docvec, wp, bp, y, wa_l, ba_l, wa_h, uw, us, out);
}

// round 15
// speedup vs baseline: 1.4913x; 1.4913x over previous
#include <cuda_runtime.h>
#include <cuda_bf16.h>
#include <math.h>
#include <stdint.h>
#include <stddef.h>

// Problem dims (fixed by the dataset)
#define BD   2560
#define SW   50
#define EW   200
#define HH   128
#define BB   64
#define DD   40
#define GC   256
#define CC   128

typedef unsigned long long ull;

// ---------------- packed fp32x2 helpers ----------------
__device__ __forceinline__ ull ffma2(ull a, ull b, ull c) {
    ull d;
    asm("fma.rn.f32x2 %0, %1, %2, %3;" : "=l"(d) : "l"(a), "l"(b), "l"(c));
    return d;
}
__device__ __forceinline__ ull pack2(float x, float y) {
    ull d;
    asm("mov.b64 %0, {%1, %2};" : "=l"(d) : "r"(__float_as_uint(x)), "r"(__float_as_uint(y)));
    return d;
}
__device__ __forceinline__ float2 unpack2(ull v) {
    unsigned lo, hi;
    asm("mov.b64 {%0, %1}, %2;" : "=r"(lo), "=r"(hi) : "l"(v));
    float2 r; r.x = __uint_as_float(lo); r.y = __uint_as_float(hi);
    return r;
}

// ---------------- mma.sync bf16 + ldmatrix (sm_80+ PTX, valid on sm_103) ---------
__device__ __forceinline__ void mma16816(float* c, const uint32_t* a, const uint32_t* b) {
    asm volatile(
        "mma.sync.aligned.m16n8k16.row.col.f32.bf16.bf16.f32 "
        "{%0,%1,%2,%3}, {%4,%5,%6,%7}, {%8,%9}, {%0,%1,%2,%3};"
        : "+f"(c[0]), "+f"(c[1]), "+f"(c[2]), "+f"(c[3])
        : "r"(a[0]), "r"(a[1]), "r"(a[2]), "r"(a[3]), "r"(b[0]), "r"(b[1]));
}
__device__ __forceinline__ void ldsm_x4(uint32_t* r, uint32_t addr) {
    asm volatile("ldmatrix.sync.aligned.m8n8.x4.shared.b16 {%0,%1,%2,%3}, [%4];"
                 : "=r"(r[0]), "=r"(r[1]), "=r"(r[2]), "=r"(r[3]) : "r"(addr));
}
__device__ __forceinline__ void ldsm_x4t(uint32_t* r, uint32_t addr) {
    asm volatile("ldmatrix.sync.aligned.m8n8.x4.trans.shared.b16 {%0,%1,%2,%3}, [%4];"
                 : "=r"(r[0]), "=r"(r[1]), "=r"(r[2]), "=r"(r[3]) : "r"(addr));
}
__device__ __forceinline__ uint32_t smem_u32(const void* p) {
    uint32_t a;
    asm("{ .reg .u64 t; cvta.to.shared.u64 t, %1; cvt.u32.u64 %0, t; }" : "=r"(a) : "l"(p));
    return a;
}
__device__ __forceinline__ uint32_t pack_bf16(float x, float y) {
    __nv_bfloat16 hx = __float2bfloat16(x), hy = __float2bfloat16(y);
    return (uint32_t)*(uint16_t*)&hx | ((uint32_t)*(uint16_t*)&hy << 16);
}

// ---------------- scratch (device globals) ----------------
__device__ float g_XWg_f[(size_t)BD*SW*GC];
__device__ float g_XWc_f[(size_t)BD*SW*CC];
__device__ float g_XWg_b[(size_t)BD*SW*GC];
__device__ float g_XWc_b[(size_t)BD*SW*CC];
__device__ float g_low  [(size_t)BD*SW*GC];
__device__ float g_proj [(size_t)BD*SW*CC];
__device__ float g_sent[BD*GC];
__device__ float g_sXWg_f[BB*DD*GC];
__device__ float g_sXWc_f[BB*DD*CC];
__device__ float g_sXWg_b[BB*DD*GC];
__device__ float g_sXWc_b[BB*DD*CC];
__device__ float g_high[BB*DD*GC];
__device__ float g_docvec[BB*GC];

// ============ tensor-core GEMM (split-bf16, mma.sync + ldmatrix) ================
// C[m0:m0+128, n0:n0+128] = A @ W + bias; fp32 = bf16hi+bf16lo; products
// AhiBhi + AloBhi + AhiBlo accumulated f32. 8 warps x (32x64) subtiles.
// A tile stored [m][k] stride 40 (conflict-free ldmatrix); B tile stored [k][n]
// stride 136 (coalesced fill, conflict-free ldmatrix.trans).
#define KCH 32
#define AST 40
#define BST 136

__global__ void __launch_bounds__(256, 2)
hgemm_bias(const float* __restrict__ A, const float* __restrict__ W,
           const float* __restrict__ bias, float* __restrict__ C,
           int srcK, int Nout, int act)
{
    __shared__ __align__(16) __nv_bfloat16 sAhi[128 * AST];
    __shared__ __align__(16) __nv_bfloat16 sAlo[128 * AST];
    __shared__ __align__(16) __nv_bfloat16 sBhi[KCH * BST];
    __shared__ __align__(16) __nv_bfloat16 sBlo[KCH * BST];

    const int tid = threadIdx.x;
    const int wid = tid >> 5, lane = tid & 31;
    const int wr = wid & 3, wc = wid >> 2;
    const int gid = lane >> 2, tig = lane & 3;
    const int m0 = blockIdx.x * 128;
    const int n0 = blockIdx.y * 128;

    // ldmatrix per-lane base addresses (bytes)
    const uint32_t aRow = wr * 32 + (lane & 15);
    const uint32_t aCol = (lane >> 4) * 8;
    const uint32_t aHiBase = smem_u32(sAhi) + (aRow * AST + aCol) * 2;
    const uint32_t aLoBase = smem_u32(sAlo) + (aRow * AST + aCol) * 2;
    const uint32_t bRow = (lane & 15);
    const uint32_t bCol = wc * 64 + (lane >> 4) * 8;
    const uint32_t bHiBase = smem_u32(sBhi) + (bRow * BST + bCol) * 2;
    const uint32_t bLoBase = smem_u32(sBlo) + (bRow * BST + bCol) * 2;

    float acc[2][8][4];
#pragma unroll
    for (int mt = 0; mt < 2; mt++)
#pragma unroll
        for (int nt = 0; nt < 8; nt++)
#pragma unroll
            for (int i = 0; i < 4; i++) acc[mt][nt][i] = 0.f;

    const int nch = (srcK + KCH - 1) / KCH;
    for (int ch = 0; ch < nch; ch++) {
        const int kb = ch * KCH;
        __syncthreads();
        // ---- fill A tile [128 x 32] hi/lo : float4 reads, 8B stores ----
        for (int idx = tid; idx < 128 * 8; idx += 256) {
            int r = idx >> 3, kq = (idx & 7) * 4;
            float4 x = make_float4(0.f, 0.f, 0.f, 0.f);
            if (kb + kq < srcK) x = *(const float4*)(A + (size_t)(m0 + r) * srcK + kb + kq);
            float h0f = __bfloat162float(__float2bfloat16(x.x));
            float h1f = __bfloat162float(__float2bfloat16(x.y));
            float h2f = __bfloat162float(__float2bfloat16(x.z));
            float h3f = __bfloat162float(__float2bfloat16(x.w));
            uint2 hv, lv;
            hv.x = pack_bf16(x.x, x.y);            hv.y = pack_bf16(x.z, x.w);
            lv.x = pack_bf16(x.x - h0f, x.y - h1f); lv.y = pack_bf16(x.z - h2f, x.w - h3f);
            *(uint2*)&sAhi[r * AST + kq] = hv;
            *(uint2*)&sAlo[r * AST + kq] = lv;
        }
        // ---- fill B tile [32 x 128] hi/lo : coalesced float4 reads along n ----
        for (int idx = tid; idx < KCH * 32; idx += 256) {
            int kr = idx >> 5, nq = (idx & 31) * 4;
            float4 x = make_float4(0.f, 0.f, 0.f, 0.f);
            if (kb + kr < srcK) x = *(const float4*)(W + (size_t)(kb + kr) * Nout + n0 + nq);
            float h0f = __bfloat162float(__float2bfloat16(x.x));
            float h1f = __bfloat162float(__float2bfloat16(x.y));
            float h2f = __bfloat162float(__float2bfloat16(x.z));
            float h3f = __bfloat162float(__float2bfloat16(x.w));
            uint2 hv, lv;
            hv.x = pack_bf16(x.x, x.y);            hv.y = pack_bf16(x.z, x.w);
            lv.x = pack_bf16(x.x - h0f, x.y - h1f); lv.y = pack_bf16(x.z - h2f, x.w - h3f);
            *(uint2*)&sBhi[kr * BST + nq] = hv;
            *(uint2*)&sBlo[kr * BST + nq] = lv;
        }
        __syncthreads();

#pragma unroll
        for (int ks = 0; ks < 2; ks++) {
            uint32_t ah[2][4], al[2][4];
#pragma unroll
            for (int mt = 0; mt < 2; mt++) {
                ldsm_x4(ah[mt], aHiBase + mt * (16 * AST * 2) + ks * 32);
                ldsm_x4(al[mt], aLoBase + mt * (16 * AST * 2) + ks * 32);
            }
#pragma unroll
            for (int ntp = 0; ntp < 4; ntp++) {
                uint32_t bh[4], bl[4];
                ldsm_x4t(bh, bHiBase + ntp * 32 + ks * (16 * BST * 2));
                ldsm_x4t(bl, bLoBase + ntp * 32 + ks * (16 * BST * 2));
#pragma unroll
                for (int half = 0; half < 2; half++) {
                    const uint32_t* bhp = bh + half * 2;
                    const uint32_t* blp = bl + half * 2;
                    const int nt = ntp * 2 + half;
#pragma unroll
                    for (int mt = 0; mt < 2; mt++) {
                        mma16816(acc[mt][nt], ah[mt], bhp);
                        mma16816(acc[mt][nt], al[mt], bhp);
                        mma16816(acc[mt][nt], ah[mt], blp);
                    }
                }
            }
        }
    }

    // epilogue: bias + optional tanh, f32 stores
#pragma unroll
    for (int mt = 0; mt < 2; mt++) {
        int r = m0 + wr * 32 + mt * 16 + gid;
#pragma unroll
        for (int nt = 0; nt < 8; nt++) {
            int col = n0 + wc * 64 + nt * 8 + tig * 2;
            float b0 = bias[col], b1 = bias[col + 1];
            float2 v0, v1;
            v0.x = acc[mt][nt][0] + b0; v0.y = acc[mt][nt][1] + b1;
            v1.x = acc[mt][nt][2] + b0; v1.y = acc[mt][nt][3] + b1;
            if (act) {
                v0.x = tanhf(v0.x); v0.y = tanhf(v0.y);
                v1.x = tanhf(v1.x); v1.y = tanhf(v1.y);
            }
            *(float2*)(C + (size_t)r * Nout + col) = v0;
            *(float2*)(C + (size_t)(r + 8) * Nout + col) = v1;
        }
    }
}

// ---------------- WORD-LEVEL BiGRU: 512 threads, resident weights ----------------
#define WSPB 20
__global__ void __launch_bounds__(512, 1)
gru_word_kernel(
    const float* __restrict__ XWg0, const float* __restrict__ XWg1,
    const float* __restrict__ XWc0, const float* __restrict__ XWc1,
    const float* __restrict__ Wgh0, const float* __restrict__ Wgh1,
    const float* __restrict__ Wch0, const float* __restrict__ Wch1,
    const int*   __restrict__ lens,
    float* __restrict__ outp, int T)
{
    const int dir = blockIdx.y;
    const float* XWg = dir ? XWg1 : XWg0;
    const float* XWc = dir ? XWc1 : XWc0;
    const float* Wgh = dir ? Wgh1 : Wgh0;
    const float* Wch = dir ? Wch1 : Wch0;
    const int col_off = dir * CC;

    extern __shared__ float smemf[];
    float* swg = smemf;
    float* swc = swg + HH * GC;
    float* sh  = swc + HH * CC;
    float* srh = sh  + WSPB * HH;
    float* sz  = srh + WSPB * HH;
    int*   slen = (int*)(sz + WSPB * HH);

    const int tid = threadIdx.x;
    const int nb  = blockIdx.x * WSPB;
    if (tid < WSPB) slen[tid] = lens[nb + tid];

    {
        const float4* src = (const float4*)Wgh;
        float4* dst = (float4*)swg;
        for (int i = tid; i < HH * GC / 4; i += 512) dst[i] = src[i];
        src = (const float4*)Wch;
        dst = (float4*)swc;
        for (int i = tid; i < HH * CC / 4; i += 512) dst[i] = src[i];
    }
    for (int i = tid; i < WSPB * HH; i += 512) sh[i] = 0.f;
    __syncthreads();

    const int ct = tid & 63;
    const int rt = tid >> 6;
    const int j0 = ct * 4;
    const int j2 = ct * 2;
    const int srn = (rt < 4) ? 3 : 2;
    const int s0  = (rt < 4) ? rt * 3 : 12 + (rt - 4) * 2;

    for (int t = 0; t < T; t++) {
        int   te_s[3]; bool val_s[3];
        float4 xg[3]; float2 xc[3];
#pragma unroll
        for (int s = 0; s < 3; s++) {
            if (s < srn) {
                int sl = s0 + s;
                int L  = slen[sl];
                bool valid = (t < L);
                int te = dir ? (valid ? (L - 1 - t) : t) : t;
                te_s[s] = te; val_s[s] = valid;
                int n = nb + sl;
                xg[s] = *(const float4*)(XWg + ((size_t)n * T + te) * GC + j0);
                xc[s] = *(const float2*)(XWc + ((size_t)n * T + te) * CC + j2);
            }
        }

        ull a0[3], a1[3];
#pragma unroll
        for (int s = 0; s < 3; s++) { a0[s] = 0ull; a1[s] = 0ull; }

#pragma unroll 4
        for (int kc = 0; kc < HH; kc += 4) {
            ulonglong2 w0 = *(const ulonglong2*)(swg + (size_t)(kc + 0) * GC + j0);
            ulonglong2 w1 = *(const ulonglong2*)(swg + (size_t)(kc + 1) * GC + j0);
            ulonglong2 w2 = *(const ulonglong2*)(swg + (size_t)(kc + 2) * GC + j0);
            ulonglong2 w3 = *(const ulonglong2*)(swg + (size_t)(kc + 3) * GC + j0);
#pragma unroll
            for (int s = 0; s < 3; s++) {
                if (s < srn) {
                    float4 hv = *(const float4*)(sh + (s0 + s) * HH + kc);
                    ull ap;
                    ap = pack2(hv.x, hv.x);
                    a0[s] = ffma2(ap, w0.x, a0[s]); a1[s] = ffma2(ap, w0.y, a1[s]);
                    ap = pack2(hv.y, hv.y);
                    a0[s] = ffma2(ap, w1.x, a0[s]); a1[s] = ffma2(ap, w1.y, a1[s]);
                    ap = pack2(hv.z, hv.z);
                    a0[s] = ffma2(ap, w2.x, a0[s]); a1[s] = ffma2(ap, w2.y, a1[s]);
                    ap = pack2(hv.w, hv.w);
                    a0[s] = ffma2(ap, w3.x, a0[s]); a1[s] = ffma2(ap, w3.y, a1[s]);
                }
            }
        }

#pragma unroll
        for (int s = 0; s < 3; s++) {
            if (s < srn) {
                int sl = s0 + s;
                float2 g01 = unpack2(a0[s]);
                float2 g23 = unpack2(a1[s]);
                float v0 = 1.f / (1.f + expf(-(g01.x + xg[s].x)));
                float v1 = 1.f / (1.f + expf(-(g01.y + xg[s].y)));
                float v2 = 1.f / (1.f + expf(-(g23.x + xg[s].z)));
                float v3 = 1.f / (1.f + expf(-(g23.y + xg[s].w)));
                if (ct < 32) {
                    float4 hv = *(const float4*)(sh + sl * HH + j0);
                    float4 o; o.x = v0 * hv.x; o.y = v1 * hv.y; o.z = v2 * hv.z; o.w = v3 * hv.w;
                    *(float4*)(srh + sl * HH + j0) = o;
                } else {
                    float4 o; o.x = v0; o.y = v1; o.z = v2; o.w = v3;
                    *(float4*)(sz + sl * HH + (j0 - 128)) = o;
                }
            }
        }
        __syncthreads();

        ull c2[3];
#pragma unroll
        for (int s = 0; s < 3; s++) c2[s] = 0ull;

#pragma unroll 4
        for (int kc = 0; kc < HH; kc += 4) {
            ull w0 = *(const ull*)(swc + (size_t)(kc + 0) * CC + j2);
            ull w1 = *(const ull*)(swc + (size_t)(kc + 1) * CC + j2);
            ull w2 = *(const ull*)(swc + (size_t)(kc + 2) * CC + j2);
            ull w3 = *(const ull*)(swc + (size_t)(kc + 3) * CC + j2);
#pragma unroll
            for (int s = 0; s < 3; s++) {
                if (s < srn) {
                    float4 rv = *(const float4*)(srh + (s0 + s) * HH + kc);
                    c2[s] = ffma2(pack2(rv.x, rv.x), w0, c2[s]);
                    c2[s] = ffma2(pack2(rv.y, rv.y), w1, c2[s]);
                    c2[s] = ffma2(pack2(rv.z, rv.z), w2, c2[s]);
                    c2[s] = ffma2(pack2(rv.w, rv.w), w3, c2[s]);
                }
            }
        }

#pragma unroll
        for (int s = 0; s < 3; s++) {
            if (s < srn) {
                int sl = s0 + s;
                int n  = nb + sl;
                bool valid = val_s[s];
                int te = te_s[s];
                float2 cc = unpack2(c2[s]);
                float c0 = tanhf(cc.x + xc[s].x);
                float c1 = tanhf(cc.y + xc[s].y);
                float2 zv = *(const float2*)(sz + sl * HH + j2);
                float2 hv = *(const float2*)(sh + sl * HH + j2);
                float hn0 = zv.x * hv.x + (1.f - zv.x) * c0;
                float hn1 = zv.y * hv.y + (1.f - zv.y) * c1;
                float2 hw; hw.x = valid ? hn0 : hv.x; hw.y = valid ? hn1 : hv.y;
                *(float2*)(sh + sl * HH + j2) = hw;
                float2 ov; ov.x = valid ? hn0 : 0.f; ov.y = valid ? hn1 : 0.f;
                *(float2*)(outp + ((size_t)n * T + te) * GC + col_off + j2) = ov;
            }
        }
        __syncthreads();
    }
}

// ---------------- sentence-level BiGRU: 256 threads, resident weights ------------
template<int SPB>
__global__ void __launch_bounds__(256, 1)
gru_resident_kernel(
    const float* __restrict__ XWg0, const float* __restrict__ XWg1,
    const float* __restrict__ XWc0, const float* __restrict__ XWc1,
    const float* __restrict__ Wgh0, const float* __restrict__ Wgh1,
    const float* __restrict__ Wch0, const float* __restrict__ Wch1,
    const int*   __restrict__ lens,
    float* __restrict__ outp, int T)
{
    constexpr int SR = SPB / 4;
    const int dir = blockIdx.y;
    const float* XWg = dir ? XWg1 : XWg0;
    const float* XWc = dir ? XWc1 : XWc0;
    const float* Wgh = dir ? Wgh1 : Wgh0;
    const float* Wch = dir ? Wch1 : Wch0;
    const int col_off = dir * CC;

    extern __shared__ float smemf[];
    float* swg = smemf;
    float* swc = swg + HH * GC;
    float* sh  = swc + HH * CC;
    float* srh = sh  + SPB * HH;
    float* sz  = srh + SPB * HH;
    int*   slen = (int*)(sz + SPB * HH);

    const int tid = threadIdx.x;
    const int nb  = blockIdx.x * SPB;
    if (tid < SPB) slen[tid] = lens[nb + tid];

    {
        const float4* src = (const float4*)Wgh;
        float4* dst = (float4*)swg;
        for (int i = tid; i < HH * GC / 4; i += 256) dst[i] = src[i];
        src = (const float4*)Wch;
        dst = (float4*)swc;
        for (int i = tid; i < HH * CC / 4; i += 256) dst[i] = src[i];
    }
    for (int i = tid; i < SPB * HH; i += 256) sh[i] = 0.f;
    __syncthreads();

    const int ct = tid & 63, rt = tid >> 6;
    const int j0 = ct * 4;
    const int j2 = ct * 2;
    const int s0 = rt * SR;

    for (int t = 0; t < T; t++) {
        ull accg[SR][2];
#pragma unroll
        for (int s = 0; s < SR; s++) { accg[s][0] = 0ull; accg[s][1] = 0ull; }

#pragma unroll 4
        for (int kc = 0; kc < HH; kc += 4) {
            ulonglong2 w0 = *(const ulonglong2*)(swg + (size_t)(kc + 0) * GC + j0);
            ulonglong2 w1 = *(const ulonglong2*)(swg + (size_t)(kc + 1) * GC + j0);
            ulonglong2 w2 = *(const ulonglong2*)(swg + (size_t)(kc + 2) * GC + j0);
            ulonglong2 w3 = *(const ulonglong2*)(swg + (size_t)(kc + 3) * GC + j0);
#pragma unroll
            for (int s = 0; s < SR; s++) {
                float4 hv = *(const float4*)(sh + (s0 + s) * HH + kc);
                ull ap;
                ap = pack2(hv.x, hv.x);
                accg[s][0] = ffma2(ap, w0.x, accg[s][0]); accg[s][1] = ffma2(ap, w0.y, accg[s][1]);
                ap = pack2(hv.y, hv.y);
                accg[s][0] = ffma2(ap, w1.x, accg[s][0]); accg[s][1] = ffma2(ap, w1.y, accg[s][1]);
                ap = pack2(hv.z, hv.z);
                accg[s][0] = ffma2(ap, w2.x, accg[s][0]); accg[s][1] = ffma2(ap, w2.y, accg[s][1]);
                ap = pack2(hv.w, hv.w);
                accg[s][0] = ffma2(ap, w3.x, accg[s][0]); accg[s][1] = ffma2(ap, w3.y, accg[s][1]);
            }
        }

#pragma unroll
        for (int s = 0; s < SR; s++) {
            int sl = s0 + s;
            int n  = nb + sl;
            int L  = slen[sl];
            int te = dir ? ((t < L) ? (L - 1 - t) : t) : t;
            float4 xg = *(const float4*)(XWg + ((size_t)n * T + te) * GC + j0);
            float2 g01 = unpack2(accg[s][0]);
            float2 g23 = unpack2(accg[s][1]);
            float v0 = 1.f / (1.f + expf(-(g01.x + xg.x)));
            float v1 = 1.f / (1.f + expf(-(g01.y + xg.y)));
            float v2 = 1.f / (1.f + expf(-(g23.x + xg.z)));
            float v3 = 1.f / (1.f + expf(-(g23.y + xg.w)));
            if (ct < 32) {
                float4 hv = *(const float4*)(sh + sl * HH + j0);
                float4 o; o.x = v0 * hv.x; o.y = v1 * hv.y; o.z = v2 * hv.z; o.w = v3 * hv.w;
                *(float4*)(srh + sl * HH + j0) = o;
            } else {
                float4 o; o.x = v0; o.y = v1; o.z = v2; o.w = v3;
                *(float4*)(sz + sl * HH + (j0 - 128)) = o;
            }
        }
        __syncthreads();

        ull accc[SR];
#pragma unroll
        for (int s = 0; s < SR; s++) accc[s] = 0ull;

#pragma unroll 4
        for (int kc = 0; kc < HH; kc += 4) {
            ull w0 = *(const ull*)(swc + (size_t)(kc + 0) * CC + j2);
            ull w1 = *(const ull*)(swc + (size_t)(kc + 1) * CC + j2);
            ull w2 = *(const ull*)(swc + (size_t)(kc + 2) * CC + j2);
            ull w3 = *(const ull*)(swc + (size_t)(kc + 3) * CC + j2);
#pragma unroll
            for (int s = 0; s < SR; s++) {
                float4 hv = *(const float4*)(srh + (s0 + s) * HH + kc);
                accc[s] = ffma2(pack2(hv.x, hv.x), w0, accc[s]);
                accc[s] = ffma2(pack2(hv.y, hv.y), w1, accc[s]);
                accc[s] = ffma2(pack2(hv.z, hv.z), w2, accc[s]);
                accc[s] = ffma2(pack2(hv.w, hv.w), w3, accc[s]);
            }
        }

#pragma unroll
        for (int s = 0; s < SR; s++) {
            int sl = s0 + s;
            int n  = nb + sl;
            int L  = slen[sl];
            bool valid = (t < L);
            int te = dir ? (valid ? (L - 1 - t) : t) : t;
            float2 xc = *(const float2*)(XWc + ((size_t)n * T + te) * CC + j2);
            float2 cc = unpack2(accc[s]);
            float c0 = tanhf(cc.x + xc.x);
            float c1 = tanhf(cc.y + xc.y);
            float z0 = sz[sl * HH + j2], z1 = sz[sl * HH + j2 + 1];
            float h0 = sh[sl * HH + j2], h1 = sh[sl * HH + j2 + 1];
            float hn0 = z0 * h0 + (1.f - z0) * c0;
            float hn1 = z1 * h1 + (1.f - z1) * c1;
            float2 hw; hw.x = valid ? hn0 : h0; hw.y = valid ? hn1 : h1;
            *(float2*)(sh + sl * HH + j2) = hw;
            float2 ov; ov.x = valid ? hn0 : 0.f; ov.y = valid ? hn1 : 0.f;
            *(float2*)(outp + ((size_t)n * T + te) * GC + col_off + j2) = ov;
        }
        __syncthreads();
    }
}

// ---------------- attention ------------------------------------------------------
__global__ void attention_kernel(const float* __restrict__ proj,
                                 const float* __restrict__ u,
                                 const float* __restrict__ seq,
                                 float* __restrict__ vec,
                                 float* __restrict__ att_out,
                                 int N, int T)
{
    const int n = blockIdx.x;
    const int tid = threadIdx.x;
    const int warp = tid >> 5, lane = tid & 31;
    __shared__ float su[128];
    __shared__ float sc[64];
    __shared__ float red[2];
    if (tid < 128) su[tid] = u[tid];
    __syncthreads();

    for (int t = warp; t < T; t += 8) {
        const float* pr = proj + ((size_t)n * T + t) * 128;
        float p = 0.f;
#pragma unroll
        for (int i = 0; i < 4; i++) p += pr[lane + i * 32] * su[lane + i * 32];
#pragma unroll
        for (int o = 16; o > 0; o >>= 1) p += __shfl_xor_sync(0xffffffffu, p, o);
        if (lane == 0) sc[t] = p;
    }
    __syncthreads();
    if (tid == 0) {
        float m = sc[0];
        for (int t = 1; t < T; t++) m = fmaxf(m, sc[t]);
        float s = 0.f;
        for (int t = 0; t < T; t++) s += expf(sc[t] - m);
        red[0] = m; red[1] = s;
    }
    __syncthreads();
    if (tid < T) {
        float a = expf(sc[tid] - red[0]) / red[1];
        att_out[(size_t)n * T + tid] = a;
        sc[tid] = a;
    }
    __syncthreads();
    {
        int c = tid;
        float a = 0.f;
        for (int t = 0; t < T; t++) a += sc[t] * seq[((size_t)n * T + t) * 256 + c];
        vec[(size_t)n * 256 + c] = a;
    }
}

// ---------------- final ----------------------------------------------------------
__global__ void final_kernel(const float* __restrict__ docvec, const float* __restrict__ wp,
                             const float* __restrict__ bp, const int* __restrict__ y,
                             const float* __restrict__ wa_l, const float* __restrict__ ba_l,
                             const float* __restrict__ wa_h, const float* __restrict__ uw,
                             const float* __restrict__ us, float* __restrict__ out)
{
    __shared__ float slog[640];
    __shared__ float red[256];
    __shared__ float lossb[64];
    __shared__ int corr[64];
    const int tid = threadIdx.x;

    for (int idx = tid; idx < 640; idx += 256) {
        int b = idx / 10, c = idx % 10;
        float a = bp[c];
        for (int k = 0; k < 256; k++) a += docvec[b * 256 + k] * wp[k * 10 + c];
        slog[idx] = a;
    }
    __syncthreads();
    if (tid < 64) {
        int b = tid;
        float m = slog[b * 10]; int am = 0;
        for (int c = 1; c < 10; c++) { float v = slog[b * 10 + c]; if (v > m) { m = v; am = c; } }
        float s = 0.f;
        for (int c = 0; c < 10; c++) s += expf(slog[b * 10 + c] - m);
        float lse = m + logf(s);
        int yb = y[b];
        lossb[b] = lse - slog[b * 10 + yb];
        corr[b]  = (am == yb) ? 1 : 0;
        out[1 + b] = (float)am;
    }
    float r = 0.f;
    for (int i = tid; i < 256 * 128; i += 256) {
        float v = wa_l[i]; r += v * v;
        float w = wa_h[i]; r += 2.f * w * w;
    }
    for (int i = tid; i < 128; i += 256) {
        float v = ba_l[i]; r += v * v;
        float a = uw[i];   r += a * a;
        float b2 = us[i];  r += b2 * b2;
    }
    red[tid] = r;
    __syncthreads();
    for (int o = 128; o > 0; o >>= 1) { if (tid < o) red[tid] += red[tid + o]; __syncthreads(); }
    if (tid == 0) {
        float L = 0.f; int C = 0;
        for (int b = 0; b < 64; b++) { L += lossb[b]; C += corr[b]; }
        out[0]  = L / 64.f + 0.01f * red[0];
        out[65] = (float)C / 64.f;
    }
}

// =================================================================================
extern "C" void kernel_launch(void* const* d_in, const int* in_sizes, int n_in,
                              void* d_out, int out_size)
{
    (void)in_sizes; (void)out_size;
    const float* X    = (const float*)d_in[0];
    const int*   y    = (const int*)d_in[1];
    const int*   slen = (const int*)d_in[2];
    const int*   dlen = (const int*)d_in[3];
    const int wo = (n_in >= 30) ? 6 : (n_in - 24);
    const float* Wt[24];
    for (int i = 0; i < 24; i++) Wt[i] = (const float*)d_in[wo + i];
    const float *wgf_l = Wt[0],  *bgf_l = Wt[1],  *wcf_l = Wt[2],  *bcf_l = Wt[3];
    const float *wgb_l = Wt[4],  *bgb_l = Wt[5],  *wcb_l = Wt[6],  *bcb_l = Wt[7];
    const float *wa_l  = Wt[8],  *ba_l  = Wt[9];
    const float *wgf_h = Wt[10], *bgf_h = Wt[11], *wcf_h = Wt[12], *bcf_h = Wt[13];
    const float *wgb_h = Wt[14], *bgb_h = Wt[15], *wcb_h = Wt[16], *bcb_h = Wt[17];
    const float *wa_h  = Wt[18], *ba_h  = Wt[19];
    const float *uw = Wt[20], *us = Wt[21], *wp = Wt[22], *bp = Wt[23];
    float* out = (float*)d_out;

    float *XWg_f, *XWc_f, *XWg_b, *XWc_b, *low, *proj, *sent;
    float *sXWg_f, *sXWc_f, *sXWg_b, *sXWc_b, *high, *docvec;
    cudaGetSymbolAddress((void**)&XWg_f, g_XWg_f);
    cudaGetSymbolAddress((void**)&XWc_f, g_XWc_f);
    cudaGetSymbolAddress((void**)&XWg_b, g_XWg_b);
    cudaGetSymbolAddress((void**)&XWc_b, g_XWc_b);
    cudaGetSymbolAddress((void**)&low,   g_low);
    cudaGetSymbolAddress((void**)&proj,  g_proj);
    cudaGetSymbolAddress((void**)&sent,  g_sent);
    cudaGetSymbolAddress((void**)&sXWg_f, g_sXWg_f);
    cudaGetSymbolAddress((void**)&sXWc_f, g_sXWc_f);
    cudaGetSymbolAddress((void**)&sXWg_b, g_sXWg_b);
    cudaGetSymbolAddress((void**)&sXWc_b, g_sXWc_b);
    cudaGetSymbolAddress((void**)&high,  g_high);
    cudaGetSymbolAddress((void**)&docvec, g_docvec);

    const int smem_w = (HH * GC + HH * CC + 3 * WSPB * HH) * 4 + WSPB * 4;  // 227,408 B
    const int smem_s = (HH * GC + HH * CC + 3 * 4 * HH) * 4 + 4 * 4;
    cudaFuncSetAttribute(gru_word_kernel, cudaFuncAttributeMaxDynamicSharedMemorySize, smem_w);
    cudaFuncSetAttribute(gru_resident_kernel<4>, cudaFuncAttributeMaxDynamicSharedMemorySize, smem_s);

    const int MW = BD * SW / 128;   // 1000 word-level M-tiles
    const int MS = BB * DD / 128;   // 20 sentence-level M-tiles

    // 1) word-level input precompute (mma.sync + ldmatrix, split-bf16)
    hgemm_bias<<<dim3(MW, 2), 256>>>(X, wgf_l, bgf_l, XWg_f, EW, GC, 0);
    hgemm_bias<<<dim3(MW, 1), 256>>>(X, wcf_l, bcf_l, XWc_f, EW, CC, 0);
    hgemm_bias<<<dim3(MW, 2), 256>>>(X, wgb_l, bgb_l, XWg_b, EW, GC, 0);
    hgemm_bias<<<dim3(MW, 1), 256>>>(X, wcb_l, bcb_l, XWc_b, EW, CC, 0);

    // 2) word-level BiGRU
    gru_word_kernel<<<dim3(BD / WSPB, 2), 512, smem_w>>>(
        XWg_f, XWg_b, XWc_f, XWc_b,
        wgf_l + (size_t)EW * GC, wgb_l + (size_t)EW * GC,
        wcf_l + (size_t)EW * CC, wcb_l + (size_t)EW * CC,
        slen, low, SW);

    // 3) word attention
    hgemm_bias<<<dim3(MW, 1), 256>>>(low, wa_l, ba_l, proj, GC, CC, 1);
    attention_kernel<<<BD, 256>>>(proj, uw, low, sent, out + 66, BD, SW);

    // 4) sentence-level input precompute
    hgemm_bias<<<dim3(MS, 2), 256>>>(sent, wgf_h, bgf_h, sXWg_f, GC, GC, 0);
    hgemm_bias<<<dim3(MS, 1), 256>>>(sent, wcf_h, bcf_h, sXWc_f, GC, CC, 0);
    hgemm_bias<<<dim3(MS, 2), 256>>>(sent, wgb_h, bgb_h, sXWg_b, GC, GC, 0);
    hgemm_bias<<<dim3(MS, 1), 256>>>(sent, wcb_h, bcb_h, sXWc_b, GC, CC, 0);

    // 5) sentence-level BiGRU
    gru_resident_kernel<4><<<dim3(BB / 4, 2), 256, smem_s>>>(
        sXWg_f, sXWg_b, sXWc_f, sXWc_b,
        wgf_h + (size_t)GC * GC, wgb_h + (size_t)GC * GC,
        wcf_h + (size_t)GC * CC, wcb_h + (size_t)GC * CC,
        dlen, high, DD);

    // 6) sentence attention
    hgemm_bias<<<dim3(MS, 1), 256>>>(high, wa_h, ba_h, proj, GC, CC, 1);
    attention_kernel<<<BB, 256>>>(proj, us, high, docvec, out + 66 + BD * SW, BB, DD);

    // 7) classifier / loss / reg / predict / accuracy
    final_kernel<<<1, 256>>>(docvec, wp, bp, y, wa_l, ba_l, wa_h, uw, us, out);
}

// round 16
// speedup vs baseline: 1.5059x; 1.0098x over previous
#include <cuda_runtime.h>
#include <cuda_bf16.h>
#include <math.h>
#include <stdint.h>
#include <stddef.h>

// Problem dims (fixed by the dataset)
#define BD   2560
#define SW   50
#define EW   200
#define HH   128
#define BB   64
#define DD   40
#define GC   256
#define CC   128

typedef unsigned long long ull;

// ---------------- packed fp32x2 helpers ----------------
__device__ __forceinline__ ull ffma2(ull a, ull b, ull c) {
    ull d;
    asm("fma.rn.f32x2 %0, %1, %2, %3;" : "=l"(d) : "l"(a), "l"(b), "l"(c));
    return d;
}
__device__ __forceinline__ ull pack2(float x, float y) {
    ull d;
    asm("mov.b64 %0, {%1, %2};" : "=l"(d) : "r"(__float_as_uint(x)), "r"(__float_as_uint(y)));
    return d;
}
__device__ __forceinline__ float2 unpack2(ull v) {
    unsigned lo, hi;
    asm("mov.b64 {%0, %1}, %2;" : "=r"(lo), "=r"(hi) : "l"(v));
    float2 r; r.x = __uint_as_float(lo); r.y = __uint_as_float(hi);
    return r;
}

// ---------------- mma.sync bf16 + ldmatrix (sm_80+ PTX, valid on sm_103) ---------
__device__ __forceinline__ void mma16816(float* c, const uint32_t* a, const uint32_t* b) {
    asm volatile(
        "mma.sync.aligned.m16n8k16.row.col.f32.bf16.bf16.f32 "
        "{%0,%1,%2,%3}, {%4,%5,%6,%7}, {%8,%9}, {%0,%1,%2,%3};"
        : "+f"(c[0]), "+f"(c[1]), "+f"(c[2]), "+f"(c[3])
        : "r"(a[0]), "r"(a[1]), "r"(a[2]), "r"(a[3]), "r"(b[0]), "r"(b[1]));
}
__device__ __forceinline__ void ldsm_x4(uint32_t* r, uint32_t addr) {
    asm volatile("ldmatrix.sync.aligned.m8n8.x4.shared.b16 {%0,%1,%2,%3}, [%4];"
                 : "=r"(r[0]), "=r"(r[1]), "=r"(r[2]), "=r"(r[3]) : "r"(addr));
}
__device__ __forceinline__ void ldsm_x4t(uint32_t* r, uint32_t addr) {
    asm volatile("ldmatrix.sync.aligned.m8n8.x4.trans.shared.b16 {%0,%1,%2,%3}, [%4];"
                 : "=r"(r[0]), "=r"(r[1]), "=r"(r[2]), "=r"(r[3]) : "r"(addr));
}
__device__ __forceinline__ uint32_t smem_u32(const void* p) {
    uint32_t a;
    asm("{ .reg .u64 t; cvta.to.shared.u64 t, %1; cvt.u32.u64 %0, t; }" : "=r"(a) : "l"(p));
    return a;
}
__device__ __forceinline__ uint32_t pack_bf16(float x, float y) {
    __nv_bfloat16 hx = __float2bfloat16(x), hy = __float2bfloat16(y);
    return (uint32_t)*(uint16_t*)&hx | ((uint32_t)*(uint16_t*)&hy << 16);
}

// ---------------- scratch (device globals) ----------------
__device__ float g_XWg_f[(size_t)BD*SW*GC];
__device__ float g_XWc_f[(size_t)BD*SW*CC];
__device__ float g_XWg_b[(size_t)BD*SW*GC];
__device__ float g_XWc_b[(size_t)BD*SW*CC];
__device__ float g_low  [(size_t)BD*SW*GC];
__device__ float g_proj [(size_t)BD*SW*CC];
__device__ float g_sent[BD*GC];
__device__ float g_sXWg_f[BB*DD*GC];
__device__ float g_sXWc_f[BB*DD*CC];
__device__ float g_sXWg_b[BB*DD*GC];
__device__ float g_sXWc_b[BB*DD*CC];
__device__ float g_high[BB*DD*GC];
__device__ float g_docvec[BB*GC];

// ============ tensor-core GEMM (split-bf16, mma.sync + ldmatrix) ================
#define KCH 32
#define AST 40
#define BST 136

__global__ void __launch_bounds__(256, 2)
hgemm_bias(const float* __restrict__ A, const float* __restrict__ W,
           const float* __restrict__ bias, float* __restrict__ C,
           int srcK, int Nout, int act)
{
    __shared__ __align__(16) __nv_bfloat16 sAhi[128 * AST];
    __shared__ __align__(16) __nv_bfloat16 sAlo[128 * AST];
    __shared__ __align__(16) __nv_bfloat16 sBhi[KCH * BST];
    __shared__ __align__(16) __nv_bfloat16 sBlo[KCH * BST];

    const int tid = threadIdx.x;
    const int wid = tid >> 5, lane = tid & 31;
    const int wr = wid & 3, wc = wid >> 2;
    const int gid = lane >> 2, tig = lane & 3;
    const int m0 = blockIdx.x * 128;
    const int n0 = blockIdx.y * 128;

    const uint32_t aRow = wr * 32 + (lane & 15);
    const uint32_t aCol = (lane >> 4) * 8;
    const uint32_t aHiBase = smem_u32(sAhi) + (aRow * AST + aCol) * 2;
    const uint32_t aLoBase = smem_u32(sAlo) + (aRow * AST + aCol) * 2;
    const uint32_t bRow = (lane & 15);
    const uint32_t bCol = wc * 64 + (lane >> 4) * 8;
    const uint32_t bHiBase = smem_u32(sBhi) + (bRow * BST + bCol) * 2;
    const uint32_t bLoBase = smem_u32(sBlo) + (bRow * BST + bCol) * 2;

    float acc[2][8][4];
#pragma unroll
    for (int mt = 0; mt < 2; mt++)
#pragma unroll
        for (int nt = 0; nt < 8; nt++)
#pragma unroll
            for (int i = 0; i < 4; i++) acc[mt][nt][i] = 0.f;

    const int nch = (srcK + KCH - 1) / KCH;
    for (int ch = 0; ch < nch; ch++) {
        const int kb = ch * KCH;
        __syncthreads();
        for (int idx = tid; idx < 128 * 8; idx += 256) {
            int r = idx >> 3, kq = (idx & 7) * 4;
            float4 x = make_float4(0.f, 0.f, 0.f, 0.f);
            if (kb + kq < srcK) x = *(const float4*)(A + (size_t)(m0 + r) * srcK + kb + kq);
            float h0f = __bfloat162float(__float2bfloat16(x.x));
            float h1f = __bfloat162float(__float2bfloat16(x.y));
            float h2f = __bfloat162float(__float2bfloat16(x.z));
            float h3f = __bfloat162float(__float2bfloat16(x.w));
            uint2 hv, lv;
            hv.x = pack_bf16(x.x, x.y);            hv.y = pack_bf16(x.z, x.w);
            lv.x = pack_bf16(x.x - h0f, x.y - h1f); lv.y = pack_bf16(x.z - h2f, x.w - h3f);
            *(uint2*)&sAhi[r * AST + kq] = hv;
            *(uint2*)&sAlo[r * AST + kq] = lv;
        }
        for (int idx = tid; idx < KCH * 32; idx += 256) {
            int kr = idx >> 5, nq = (idx & 31) * 4;
            float4 x = make_float4(0.f, 0.f, 0.f, 0.f);
            if (kb + kr < srcK) x = *(const float4*)(W + (size_t)(kb + kr) * Nout + n0 + nq);
            float h0f = __bfloat162float(__float2bfloat16(x.x));
            float h1f = __bfloat162float(__float2bfloat16(x.y));
            float h2f = __bfloat162float(__float2bfloat16(x.z));
            float h3f = __bfloat162float(__float2bfloat16(x.w));
            uint2 hv, lv;
            hv.x = pack_bf16(x.x, x.y);            hv.y = pack_bf16(x.z, x.w);
            lv.x = pack_bf16(x.x - h0f, x.y - h1f); lv.y = pack_bf16(x.z - h2f, x.w - h3f);
            *(uint2*)&sBhi[kr * BST + nq] = hv;
            *(uint2*)&sBlo[kr * BST + nq] = lv;
        }
        __syncthreads();

#pragma unroll
        for (int ks = 0; ks < 2; ks++) {
            uint32_t ah[2][4], al[2][4];
#pragma unroll
            for (int mt = 0; mt < 2; mt++) {
                ldsm_x4(ah[mt], aHiBase + mt * (16 * AST * 2) + ks * 32);
                ldsm_x4(al[mt], aLoBase + mt * (16 * AST * 2) + ks * 32);
            }
#pragma unroll
            for (int ntp = 0; ntp < 4; ntp++) {
                uint32_t bh[4], bl[4];
                ldsm_x4t(bh, bHiBase + ntp * 32 + ks * (16 * BST * 2));
                ldsm_x4t(bl, bLoBase + ntp * 32 + ks * (16 * BST * 2));
#pragma unroll
                for (int half = 0; half < 2; half++) {
                    const uint32_t* bhp = bh + half * 2;
                    const uint32_t* blp = bl + half * 2;
                    const int nt = ntp * 2 + half;
#pragma unroll
                    for (int mt = 0; mt < 2; mt++) {
                        mma16816(acc[mt][nt], ah[mt], bhp);
                        mma16816(acc[mt][nt], al[mt], bhp);
                        mma16816(acc[mt][nt], ah[mt], blp);
                    }
                }
            }
        }
    }

#pragma unroll
    for (int mt = 0; mt < 2; mt++) {
        int r = m0 + wr * 32 + mt * 16 + gid;
#pragma unroll
        for (int nt = 0; nt < 8; nt++) {
            int col = n0 + wc * 64 + nt * 8 + tig * 2;
            float b0 = bias[col], b1 = bias[col + 1];
            float2 v0, v1;
            v0.x = acc[mt][nt][0] + b0; v0.y = acc[mt][nt][1] + b1;
            v1.x = acc[mt][nt][2] + b0; v1.y = acc[mt][nt][3] + b1;
            if (act) {
                v0.x = tanhf(v0.x); v0.y = tanhf(v0.y);
                v1.x = tanhf(v1.x); v1.y = tanhf(v1.y);
            }
            *(float2*)(C + (size_t)r * Nout + col) = v0;
            *(float2*)(C + (size_t)(r + 8) * Nout + col) = v1;
        }
    }
}

// ---------------- WORD-LEVEL BiGRU: 512 threads, resident weights ----------------
// rg=4 retile: 128 col-groups (ct) x 4 row-groups (rt), SR=5 seqs/thread.
// Gate: 2 cols/thread (1 ull FFMA2/k); candidate: 1 col/thread (scalar FMA).
// Halves weight crossbar traffic vs the 64x8 tiling; h reads stay warp-broadcast.
#define WSPB 20
#define WSR  5
__global__ void __launch_bounds__(512, 1)
gru_word_kernel(
    const float* __restrict__ XWg0, const float* __restrict__ XWg1,
    const float* __restrict__ XWc0, const float* __restrict__ XWc1,
    const float* __restrict__ Wgh0, const float* __restrict__ Wgh1,
    const float* __restrict__ Wch0, const float* __restrict__ Wch1,
    const int*   __restrict__ lens,
    float* __restrict__ outp, int T)
{
    const int dir = blockIdx.y;
    const float* XWg = dir ? XWg1 : XWg0;
    const float* XWc = dir ? XWc1 : XWc0;
    const float* Wgh = dir ? Wgh1 : Wgh0;
    const float* Wch = dir ? Wch1 : Wch0;
    const int col_off = dir * CC;

    extern __shared__ float smemf[];
    float* swg = smemf;                  // HH*GC
    float* swc = swg + HH * GC;          // HH*CC
    float* sh  = swc + HH * CC;          // WSPB*HH
    float* srh = sh  + WSPB * HH;        // WSPB*HH
    float* sz  = srh + WSPB * HH;        // WSPB*HH
    int*   slen = (int*)(sz + WSPB * HH);

    const int tid = threadIdx.x;
    const int nb  = blockIdx.x * WSPB;
    if (tid < WSPB) slen[tid] = lens[nb + tid];

    {
        const float4* src = (const float4*)Wgh;
        float4* dst = (float4*)swg;
        for (int i = tid; i < HH * GC / 4; i += 512) dst[i] = src[i];
        src = (const float4*)Wch;
        dst = (float4*)swc;
        for (int i = tid; i < HH * CC / 4; i += 512) dst[i] = src[i];
    }
    for (int i = tid; i < WSPB * HH; i += 512) sh[i] = 0.f;
    __syncthreads();

    const int ct = tid & 127;           // 128 col groups
    const int rt = tid >> 7;            // 4 row groups
    const int jg = ct * 2;              // gate cols [jg, jg+1]
    const int jc = ct;                  // candidate col
    const int s0 = rt * WSR;

    for (int t = 0; t < T; t++) {
        // ---- prefetch this step's XWg / XWc + masks ----
        int   te_s[WSR]; bool val_s[WSR];
        float2 xg[WSR]; float xc[WSR];
#pragma unroll
        for (int s = 0; s < WSR; s++) {
            int sl = s0 + s;
            int L  = slen[sl];
            bool valid = (t < L);
            int te = dir ? (valid ? (L - 1 - t) : t) : t;
            te_s[s] = te; val_s[s] = valid;
            int n = nb + sl;
            xg[s] = *(const float2*)(XWg + ((size_t)n * T + te) * GC + jg);
            xc[s] = XWc[((size_t)n * T + te) * CC + jc];
        }

        // ===== gate GEMM: acc[s] (packed pair for cols jg, jg+1) =====
        ull ag[WSR];
#pragma unroll
        for (int s = 0; s < WSR; s++) ag[s] = 0ull;

#pragma unroll 4
        for (int kc = 0; kc < HH; kc += 4) {
            ull w0 = *(const ull*)(swg + (size_t)(kc + 0) * GC + jg);
            ull w1 = *(const ull*)(swg + (size_t)(kc + 1) * GC + jg);
            ull w2 = *(const ull*)(swg + (size_t)(kc + 2) * GC + jg);
            ull w3 = *(const ull*)(swg + (size_t)(kc + 3) * GC + jg);
#pragma unroll
            for (int s = 0; s < WSR; s++) {
                float4 hv = *(const float4*)(sh + (s0 + s) * HH + kc);   // warp-broadcast
                ag[s] = ffma2(pack2(hv.x, hv.x), w0, ag[s]);
                ag[s] = ffma2(pack2(hv.y, hv.y), w1, ag[s]);
                ag[s] = ffma2(pack2(hv.z, hv.z), w2, ag[s]);
                ag[s] = ffma2(pack2(hv.w, hv.w), w3, ag[s]);
            }
        }

        // gate epilogue: sigmoid; ct<64 -> r cols (write r*h), else z cols (write z)
#pragma unroll
        for (int s = 0; s < WSR; s++) {
            int sl = s0 + s;
            float2 g = unpack2(ag[s]);
            float v0 = 1.f / (1.f + expf(-(g.x + xg[s].x)));
            float v1 = 1.f / (1.f + expf(-(g.y + xg[s].y)));
            if (ct < 64) {
                float2 hv = *(const float2*)(sh + sl * HH + jg);
                float2 o; o.x = v0 * hv.x; o.y = v1 * hv.y;
                *(float2*)(srh + sl * HH + jg) = o;
            } else {
                float2 o; o.x = v0; o.y = v1;
                *(float2*)(sz + sl * HH + (jg - 128)) = o;
            }
        }
        __syncthreads();

        // ===== candidate GEMM: scalar col jc =====
        float ac[WSR];
#pragma unroll
        for (int s = 0; s < WSR; s++) ac[s] = 0.f;

#pragma unroll 4
        for (int kc = 0; kc < HH; kc += 4) {
            float w0 = swc[(size_t)(kc + 0) * CC + jc];
            float w1 = swc[(size_t)(kc + 1) * CC + jc];
            float w2 = swc[(size_t)(kc + 2) * CC + jc];
            float w3 = swc[(size_t)(kc + 3) * CC + jc];
#pragma unroll
            for (int s = 0; s < WSR; s++) {
                float4 rv = *(const float4*)(srh + (s0 + s) * HH + kc);  // warp-broadcast
                ac[s] += rv.x * w0 + rv.y * w1 + rv.z * w2 + rv.w * w3;
            }
        }

        // final epilogue: c = tanh(acc + xc); h' = z*h + (1-z)*c, masked
#pragma unroll
        for (int s = 0; s < WSR; s++) {
            int sl = s0 + s;
            int n  = nb + sl;
            bool valid = val_s[s];
            int te = te_s[s];
            float c0 = tanhf(ac[s] + xc[s]);
            float z0 = sz[sl * HH + jc];
            float h0 = sh[sl * HH + jc];
            float hn0 = z0 * h0 + (1.f - z0) * c0;
            sh[sl * HH + jc] = valid ? hn0 : h0;
            outp[((size_t)n * T + te) * GC + col_off + jc] = valid ? hn0 : 0.f;
        }
        __syncthreads();
    }
}

// ---------------- sentence-level BiGRU: 256 threads, resident weights ------------
template<int SPB>
__global__ void __launch_bounds__(256, 1)
gru_resident_kernel(
    const float* __restrict__ XWg0, const float* __restrict__ XWg1,
    const float* __restrict__ XWc0, const float* __restrict__ XWc1,
    const float* __restrict__ Wgh0, const float* __restrict__ Wgh1,
    const float* __restrict__ Wch0, const float* __restrict__ Wch1,
    const int*   __restrict__ lens,
    float* __restrict__ outp, int T)
{
    constexpr int SR = SPB / 4;
    const int dir = blockIdx.y;
    const float* XWg = dir ? XWg1 : XWg0;
    const float* XWc = dir ? XWc1 : XWc0;
    const float* Wgh = dir ? Wgh1 : Wgh0;
    const float* Wch = dir ? Wch1 : Wch0;
    const int col_off = dir * CC;

    extern __shared__ float smemf[];
    float* swg = smemf;
    float* swc = swg + HH * GC;
    float* sh  = swc + HH * CC;
    float* srh = sh  + SPB * HH;
    float* sz  = srh + SPB * HH;
    int*   slen = (int*)(sz + SPB * HH);

    const int tid = threadIdx.x;
    const int nb  = blockIdx.x * SPB;
    if (tid < SPB) slen[tid] = lens[nb + tid];

    {
        const float4* src = (const float4*)Wgh;
        float4* dst = (float4*)swg;
        for (int i = tid; i < HH * GC / 4; i += 256) dst[i] = src[i];
        src = (const float4*)Wch;
        dst = (float4*)swc;
        for (int i = tid; i < HH * CC / 4; i += 256) dst[i] = src[i];
    }
    for (int i = tid; i < SPB * HH; i += 256) sh[i] = 0.f;
    __syncthreads();

    const int ct = tid & 63, rt = tid >> 6;
    const int j0 = ct * 4;
    const int j2 = ct * 2;
    const int s0 = rt * SR;

    for (int t = 0; t < T; t++) {
        ull accg[SR][2];
#pragma unroll
        for (int s = 0; s < SR; s++) { accg[s][0] = 0ull; accg[s][1] = 0ull; }

#pragma unroll 4
        for (int kc = 0; kc < HH; kc += 4) {
            ulonglong2 w0 = *(const ulonglong2*)(swg + (size_t)(kc + 0) * GC + j0);
            ulonglong2 w1 = *(const ulonglong2*)(swg + (size_t)(kc + 1) * GC + j0);
            ulonglong2 w2 = *(const ulonglong2*)(swg + (size_t)(kc + 2) * GC + j0);
            ulonglong2 w3 = *(const ulonglong2*)(swg + (size_t)(kc + 3) * GC + j0);
#pragma unroll
            for (int s = 0; s < SR; s++) {
                float4 hv = *(const float4*)(sh + (s0 + s) * HH + kc);
                ull ap;
                ap = pack2(hv.x, hv.x);
                accg[s][0] = ffma2(ap, w0.x, accg[s][0]); accg[s][1] = ffma2(ap, w0.y, accg[s][1]);
                ap = pack2(hv.y, hv.y);
                accg[s][0] = ffma2(ap, w1.x, accg[s][0]); accg[s][1] = ffma2(ap, w1.y, accg[s][1]);
                ap = pack2(hv.z, hv.z);
                accg[s][0] = ffma2(ap, w2.x, accg[s][0]); accg[s][1] = ffma2(ap, w2.y, accg[s][1]);
                ap = pack2(hv.w, hv.w);
                accg[s][0] = ffma2(ap, w3.x, accg[s][0]); accg[s][1] = ffma2(ap, w3.y, accg[s][1]);
            }
        }

#pragma unroll
        for (int s = 0; s < SR; s++) {
            int sl = s0 + s;
            int n  = nb + sl;
            int L  = slen[sl];
            int te = dir ? ((t < L) ? (L - 1 - t) : t) : t;
            float4 xg = *(const float4*)(XWg + ((size_t)n * T + te) * GC + j0);
            float2 g01 = unpack2(accg[s][0]);
            float2 g23 = unpack2(accg[s][1]);
            float v0 = 1.f / (1.f + expf(-(g01.x + xg.x)));
            float v1 = 1.f / (1.f + expf(-(g01.y + xg.y)));
            float v2 = 1.f / (1.f + expf(-(g23.x + xg.z)));
            float v3 = 1.f / (1.f + expf(-(g23.y + xg.w)));
            if (ct < 32) {
                float4 hv = *(const float4*)(sh + sl * HH + j0);
                float4 o; o.x = v0 * hv.x; o.y = v1 * hv.y; o.z = v2 * hv.z; o.w = v3 * hv.w;
                *(float4*)(srh + sl * HH + j0) = o;
            } else {
                float4 o; o.x = v0; o.y = v1; o.z = v2; o.w = v3;
                *(float4*)(sz + sl * HH + (j0 - 128)) = o;
            }
        }
        __syncthreads();

        ull accc[SR];
#pragma unroll
        for (int s = 0; s < SR; s++) accc[s] = 0ull;

#pragma unroll 4
        for (int kc = 0; kc < HH; kc += 4) {
            ull w0 = *(const ull*)(swc + (size_t)(kc + 0) * CC + j2);
            ull w1 = *(const ull*)(swc + (size_t)(kc + 1) * CC + j2);
            ull w2 = *(const ull*)(swc + (size_t)(kc + 2) * CC + j2);
            ull w3 = *(const ull*)(swc + (size_t)(kc + 3) * CC + j2);
#pragma unroll
            for (int s = 0; s < SR; s++) {
                float4 hv = *(const float4*)(srh + (s0 + s) * HH + kc);
                accc[s] = ffma2(pack2(hv.x, hv.x), w0, accc[s]);
                accc[s] = ffma2(pack2(hv.y, hv.y), w1, accc[s]);
                accc[s] = ffma2(pack2(hv.z, hv.z), w2, accc[s]);
                accc[s] = ffma2(pack2(hv.w, hv.w), w3, accc[s]);
            }
        }

#pragma unroll
        for (int s = 0; s < SR; s++) {
            int sl = s0 + s;
            int n  = nb + sl;
            int L  = slen[sl];
            bool valid = (t < L);
            int te = dir ? (valid ? (L - 1 - t) : t) : t;
            float2 xc = *(const float2*)(XWc + ((size_t)n * T + te) * CC + j2);
            float2 cc = unpack2(accc[s]);
            float c0 = tanhf(cc.x + xc.x);
            float c1 = tanhf(cc.y + xc.y);
            float z0 = sz[sl * HH + j2], z1 = sz[sl * HH + j2 + 1];
            float h0 = sh[sl * HH + j2], h1 = sh[sl * HH + j2 + 1];
            float hn0 = z0 * h0 + (1.f - z0) * c0;
            float hn1 = z1 * h1 + (1.f - z1) * c1;
            float2 hw; hw.x = valid ? hn0 : h0; hw.y = valid ? hn1 : h1;
            *(float2*)(sh + sl * HH + j2) = hw;
            float2 ov; ov.x = valid ? hn0 : 0.f; ov.y = valid ? hn1 : 0.f;
            *(float2*)(outp + ((size_t)n * T + te) * GC + col_off + j2) = ov;
        }
        __syncthreads();
    }
}

// ---------------- attention ------------------------------------------------------
__global__ void attention_kernel(const float* __restrict__ proj,
                                 const float* __restrict__ u,
                                 const float* __restrict__ seq,
                                 float* __restrict__ vec,
                                 float* __restrict__ att_out,
                                 int N, int T)
{
    const int n = blockIdx.x;
    const int tid = threadIdx.x;
    const int warp = tid >> 5, lane = tid & 31;
    __shared__ float su[128];
    __shared__ float sc[64];
    __shared__ float red[2];
    if (tid < 128) su[tid] = u[tid];
    __syncthreads();

    for (int t = warp; t < T; t += 8) {
        const float* pr = proj + ((size_t)n * T + t) * 128;
        float p = 0.f;
#pragma unroll
        for (int i = 0; i < 4; i++) p += pr[lane + i * 32] * su[lane + i * 32];
#pragma unroll
        for (int o = 16; o > 0; o >>= 1) p += __shfl_xor_sync(0xffffffffu, p, o);
        if (lane == 0) sc[t] = p;
    }
    __syncthreads();
    if (tid == 0) {
        float m = sc[0];
        for (int t = 1; t < T; t++) m = fmaxf(m, sc[t]);
        float s = 0.f;
        for (int t = 0; t < T; t++) s += expf(sc[t] - m);
        red[0] = m; red[1] = s;
    }
    __syncthreads();
    if (tid < T) {
        float a = expf(sc[tid] - red[0]) / red[1];
        att_out[(size_t)n * T + tid] = a;
        sc[tid] = a;
    }
    __syncthreads();
    {
        int c = tid;
        float a = 0.f;
        for (int t = 0; t < T; t++) a += sc[t] * seq[((size_t)n * T + t) * 256 + c];
        vec[(size_t)n * 256 + c] = a;
    }
}

// ---------------- final ----------------------------------------------------------
__global__ void final_kernel(const float* __restrict__ docvec, const float* __restrict__ wp,
                             const float* __restrict__ bp, const int* __restrict__ y,
                             const float* __restrict__ wa_l, const float* __restrict__ ba_l,
                             const float* __restrict__ wa_h, const float* __restrict__ uw,
                             const float* __restrict__ us, float* __restrict__ out)
{
    __shared__ float slog[640];
    __shared__ float red[256];
    __shared__ float lossb[64];
    __shared__ int corr[64];
    const int tid = threadIdx.x;

    for (int idx = tid; idx < 640; idx += 256) {
        int b = idx / 10, c = idx % 10;
        float a = bp[c];
        for (int k = 0; k < 256; k++) a += docvec[b * 256 + k] * wp[k * 10 + c];
        slog[idx] = a;
    }
    __syncthreads();
    if (tid < 64) {
        int b = tid;
        float m = slog[b * 10]; int am = 0;
        for (int c = 1; c < 10; c++) { float v = slog[b * 10 + c]; if (v > m) { m = v; am = c; } }
        float s = 0.f;
        for (int c = 0; c < 10; c++) s += expf(slog[b * 10 + c] - m);
        float lse = m + logf(s);
        int yb = y[b];
        lossb[b] = lse - slog[b * 10 + yb];
        corr[b]  = (am == yb) ? 1 : 0;
        out[1 + b] = (float)am;
    }
    float r = 0.f;
    for (int i = tid; i < 256 * 128; i += 256) {
        float v = wa_l[i]; r += v * v;
        float w = wa_h[i]; r += 2.f * w * w;
    }
    for (int i = tid; i < 128; i += 256) {
        float v = ba_l[i]; r += v * v;
        float a = uw[i];   r += a * a;
        float b2 = us[i];  r += b2 * b2;
    }
    red[tid] = r;
    __syncthreads();
    for (int o = 128; o > 0; o >>= 1) { if (tid < o) red[tid] += red[tid + o]; __syncthreads(); }
    if (tid == 0) {
        float L = 0.f; int C = 0;
        for (int b = 0; b < 64; b++) { L += lossb[b]; C += corr[b]; }
        out[0]  = L / 64.f + 0.01f * red[0];
        out[65] = (float)C / 64.f;
    }
}

// =================================================================================
extern "C" void kernel_launch(void* const* d_in, const int* in_sizes, int n_in,
                              void* d_out, int out_size)
{
    (void)in_sizes; (void)out_size;
    const float* X    = (const float*)d_in[0];
    const int*   y    = (const int*)d_in[1];
    const int*   slen = (const int*)d_in[2];
    const int*   dlen = (const int*)d_in[3];
    const int wo = (n_in >= 30) ? 6 : (n_in - 24);
    const float* Wt[24];
    for (int i = 0; i < 24; i++) Wt[i] = (const float*)d_in[wo + i];
    const float *wgf_l = Wt[0],  *bgf_l = Wt[1],  *wcf_l = Wt[2],  *bcf_l = Wt[3];
    const float *wgb_l = Wt[4],  *bgb_l = Wt[5],  *wcb_l = Wt[6],  *bcb_l = Wt[7];
    const float *wa_l  = Wt[8],  *ba_l  = Wt[9];
    const float *wgf_h = Wt[10], *bgf_h = Wt[11], *wcf_h = Wt[12], *bcf_h = Wt[13];
    const float *wgb_h = Wt[14], *bgb_h = Wt[15], *wcb_h = Wt[16], *bcb_h = Wt[17];
    const float *wa_h  = Wt[18], *ba_h  = Wt[19];
    const float *uw = Wt[20], *us = Wt[21], *wp = Wt[22], *bp = Wt[23];
    float* out = (float*)d_out;

    float *XWg_f, *XWc_f, *XWg_b, *XWc_b, *low, *proj, *sent;
    float *sXWg_f, *sXWc_f, *sXWg_b, *sXWc_b, *high, *docvec;
    cudaGetSymbolAddress((void**)&XWg_f, g_XWg_f);
    cudaGetSymbolAddress((void**)&XWc_f, g_XWc_f);
    cudaGetSymbolAddress((void**)&XWg_b, g_XWg_b);
    cudaGetSymbolAddress((void**)&XWc_b, g_XWc_b);
    cudaGetSymbolAddress((void**)&low,   g_low);
    cudaGetSymbolAddress((void**)&proj,  g_proj);
    cudaGetSymbolAddress((void**)&sent,  g_sent);
    cudaGetSymbolAddress((void**)&sXWg_f, g_sXWg_f);
    cudaGetSymbolAddress((void**)&sXWc_f, g_sXWc_f);
    cudaGetSymbolAddress((void**)&sXWg_b, g_sXWg_b);
    cudaGetSymbolAddress((void**)&sXWc_b, g_sXWc_b);
    cudaGetSymbolAddress((void**)&high,  g_high);
    cudaGetSymbolAddress((void**)&docvec, g_docvec);

    const int smem_w = (HH * GC + HH * CC + 3 * WSPB * HH) * 4 + WSPB * 4;  // 227,408 B
    const int smem_s = (HH * GC + HH * CC + 3 * 4 * HH) * 4 + 4 * 4;
    cudaFuncSetAttribute(gru_word_kernel, cudaFuncAttributeMaxDynamicSharedMemorySize, smem_w);
    cudaFuncSetAttribute(gru_resident_kernel<4>, cudaFuncAttributeMaxDynamicSharedMemorySize, smem_s);

    const int MW = BD * SW / 128;   // 1000 word-level M-tiles
    const int MS = BB * DD / 128;   // 20 sentence-level M-tiles

    // 1) word-level input precompute (mma.sync + ldmatrix, split-bf16)
    hgemm_bias<<<dim3(MW, 2), 256>>>(X, wgf_l, bgf_l, XWg_f, EW, GC, 0);
    hgemm_bias<<<dim3(MW, 1), 256>>>(X, wcf_l, bcf_l, XWc_f, EW, CC, 0);
    hgemm_bias<<<dim3(MW, 2), 256>>>(X, wgb_l, bgb_l, XWg_b, EW, GC, 0);
    hgemm_bias<<<dim3(MW, 1), 256>>>(X, wcb_l, bcb_l, XWc_b, EW, CC, 0);

    // 2) word-level BiGRU (rg=4 retile)
    gru_word_kernel<<<dim3(BD / WSPB, 2), 512, smem_w>>>(
        XWg_f, XWg_b, XWc_f, XWc_b,
        wgf_l + (size_t)EW * GC, wgb_l + (size_t)EW * GC,
        wcf_l + (size_t)EW * CC, wcb_l + (size_t)EW * CC,
        slen, low, SW);

    // 3) word attention
    hgemm_bias<<<dim3(MW, 1), 256>>>(low, wa_l, ba_l, proj, GC, CC, 1);
    attention_kernel<<<BD, 256>>>(proj, uw, low, sent, out + 66, BD, SW);

    // 4) sentence-level input precompute
    hgemm_bias<<<dim3(MS, 2), 256>>>(sent, wgf_h, bgf_h, sXWg_f, GC, GC, 0);
    hgemm_bias<<<dim3(MS, 1), 256>>>(sent, wcf_h, bcf_h, sXWc_f, GC, CC, 0);
    hgemm_bias<<<dim3(MS, 2), 256>>>(sent, wgb_h, bgb_h, sXWg_b, GC, GC, 0);
    hgemm_bias<<<dim3(MS, 1), 256>>>(sent, wcb_h, bcb_h, sXWc_b, GC, CC, 0);

    // 5) sentence-level BiGRU
    gru_resident_kernel<4><<<dim3(BB / 4, 2), 256, smem_s>>>(
        sXWg_f, sXWg_b, sXWc_f, sXWc_b,
        wgf_h + (size_t)GC * GC, wgb_h + (size_t)GC * GC,
        wcf_h + (size_t)GC * CC, wcb_h + (size_t)GC * CC,
        dlen, high, DD);

    // 6) sentence attention
    hgemm_bias<<<dim3(MS, 1), 256>>>(high, wa_h, ba_h, proj, GC, CC, 1);
    attention_kernel<<<BB, 256>>>(proj, us, high, docvec, out + 66 + BD * SW, BB, DD);

    // 7) classifier / loss / reg / predict / accuracy
    final_kernel<<<1, 256>>>(docvec, wp, bp, y, wa_l, ba_l, wa_h, uw, us, out);
}